// round 2
// baseline (speedup 1.0000x reference)
#include <cuda_runtime.h>
#include <math.h>

#define NN 4096
#define DD 2048
#define CC 8192
#define MARGIN_F 0.3f
#define EPSLS 0.1f

#define BM 128
#define BN 128
#define BK 16

// Scratch (no allocations allowed)
__device__ float g_xx[NN];
__device__ float g_ce_row[NN];
__device__ int   g_tgt[NN];

// ---------------- init: convert targets, init output accumulators ----------------
__global__ void k_init(const int* __restrict__ tgt, float* __restrict__ out) {
    int i = blockIdx.x * blockDim.x + threadIdx.x;
    if (i < NN) {
        int t = tgt[i];
        // defensive clamp: bad dtype shows as rel_err, not illegal access
        g_tgt[i] = min(max(t, 0), CC - 1);
        out[2 + i] = 0.0f;                       // dist_ap max-accumulator (dists >= 0)
        ((int*)out)[2 + NN + i] = 0x7F800000;    // dist_an min-accumulator = +inf bits
    }
}

// ---------------- per-row sum of squares of embeddings ----------------
__global__ void k_xx(const float* __restrict__ E) {
    int r = blockIdx.x;
    const float4* row = (const float4*)(E + (size_t)r * DD);
    float s = 0.f;
    for (int i = threadIdx.x; i < DD / 4; i += 256) {
        float4 v = row[i];
        s += v.x * v.x + v.y * v.y + v.z * v.z + v.w * v.w;
    }
    __shared__ float sm[256];
    sm[threadIdx.x] = s;
    __syncthreads();
    for (int o = 128; o > 0; o >>= 1) {
        if (threadIdx.x < o) sm[threadIdx.x] += sm[threadIdx.x + o];
        __syncthreads();
    }
    if (threadIdx.x == 0) g_xx[r] = sm[0];
}

// ---------------- label-smoothed CE, one block per row ----------------
__global__ void k_ce(const float* __restrict__ logits) {
    int r = blockIdx.x;
    int t = threadIdx.x;
    const float4* row = (const float4*)(logits + (size_t)r * CC);

    float mx = -INFINITY, s = 0.f;
    for (int i = t; i < CC / 4; i += 256) {
        float4 v = row[i];
        mx = fmaxf(mx, fmaxf(fmaxf(v.x, v.y), fmaxf(v.z, v.w)));
        s += v.x + v.y + v.z + v.w;
    }
    __shared__ float smx[256], ssm[256];
    smx[t] = mx; ssm[t] = s;
    __syncthreads();
    for (int o = 128; o > 0; o >>= 1) {
        if (t < o) {
            smx[t] = fmaxf(smx[t], smx[t + o]);
            ssm[t] += ssm[t + o];
        }
        __syncthreads();
    }
    mx = smx[0];
    s  = ssm[0];
    __syncthreads();

    float se = 0.f;
    for (int i = t; i < CC / 4; i += 256) {
        float4 v = row[i];
        se += expf(v.x - mx) + expf(v.y - mx) + expf(v.z - mx) + expf(v.w - mx);
    }
    ssm[t] = se;
    __syncthreads();
    for (int o = 128; o > 0; o >>= 1) {
        if (t < o) ssm[t] += ssm[t + o];
        __syncthreads();
    }
    if (t == 0) {
        float lse = mx + logf(ssm[0]);
        float lt  = logits[(size_t)r * CC + g_tgt[r]];
        // (1-eps)*(lse - lt) + eps*(lse - mean_logit)
        g_ce_row[r] = lse - (1.f - EPSLS) * lt - EPSLS * (s / (float)CC);
    }
}

// ---------------- fused dist GEMM + batch-hard mining epilogue ----------------
// G[i][j] = E_i . E_j ; d2 = xx[i] + xx[j] - 2G ; dist = sqrt(max(d2, 1e-12))
// per-row masked max (positives, incl diagonal) / min (negatives) -> int atomics on out
__global__ void __launch_bounds__(256) k_dist(const float* __restrict__ E,
                                              float* __restrict__ out) {
    __shared__ float As[BK][BM + 4];
    __shared__ float Bs[BK][BN + 4];
    __shared__ int   tR[BM];
    __shared__ int   tC[BN];
    __shared__ float xR[BM];
    __shared__ float xC[BN];

    int bi = blockIdx.y, bj = blockIdx.x;
    int row0 = bi * BM, col0 = bj * BN;
    int tid = threadIdx.x;
    int tx = tid & 15, ty = tid >> 4;

    if (tid < 128) {
        tR[tid] = g_tgt[row0 + tid];
        xR[tid] = g_xx[row0 + tid];
    } else {
        int j = tid - 128;
        tC[j] = g_tgt[col0 + j];
        xC[j] = g_xx[col0 + j];
    }

    float acc[8][8];
#pragma unroll
    for (int m = 0; m < 8; m++)
#pragma unroll
        for (int n = 0; n < 8; n++) acc[m][n] = 0.f;

    for (int k0 = 0; k0 < DD; k0 += BK) {
#pragma unroll
        for (int l = 0; l < 2; l++) {
            int q  = tid + l * 256;     // 512 float4 per operand tile
            int r  = q >> 2;            // 0..127
            int kq = (q & 3) << 2;      // 0,4,8,12
            float4 v = *(const float4*)(E + (size_t)(row0 + r) * DD + k0 + kq);
            As[kq + 0][r] = v.x; As[kq + 1][r] = v.y;
            As[kq + 2][r] = v.z; As[kq + 3][r] = v.w;
            float4 w = *(const float4*)(E + (size_t)(col0 + r) * DD + k0 + kq);
            Bs[kq + 0][r] = w.x; Bs[kq + 1][r] = w.y;
            Bs[kq + 2][r] = w.z; Bs[kq + 3][r] = w.w;
        }
        __syncthreads();
#pragma unroll
        for (int k = 0; k < BK; k++) {
            float a[8], b[8];
#pragma unroll
            for (int m = 0; m < 8; m++) a[m] = As[k][ty + m * 16];
#pragma unroll
            for (int n = 0; n < 8; n++) b[n] = Bs[k][tx + n * 16];
#pragma unroll
            for (int m = 0; m < 8; m++)
#pragma unroll
                for (int n = 0; n < 8; n++) acc[m][n] = fmaf(a[m], b[n], acc[m][n]);
        }
        __syncthreads();
    }

    // Epilogue: masked max/min per row-of-tile, shuffle-reduce across the 16
    // lanes sharing a ty (xor on low 4 lane bits stays within the group).
#pragma unroll
    for (int m = 0; m < 8; m++) {
        int   lr  = ty + m * 16;
        int   trg = tR[lr];
        float xr  = xR[lr];
        float mp = -INFINITY, mn = INFINITY;
#pragma unroll
        for (int n = 0; n < 8; n++) {
            int   lc  = tx + n * 16;
            float d2  = xr + xC[lc] - 2.f * acc[m][n];
            float dst = sqrtf(fmaxf(d2, 1e-12f));
            if (trg == tC[lc]) mp = fmaxf(mp, dst);
            else               mn = fminf(mn, dst);
        }
#pragma unroll
        for (int o = 8; o > 0; o >>= 1) {
            mp = fmaxf(mp, __shfl_xor_sync(0xFFFFFFFF, mp, o));
            mn = fminf(mn, __shfl_xor_sync(0xFFFFFFFF, mn, o));
        }
        if (tx == 0) {
            // dist >= 0 so float bit-pattern ordering == int ordering;
            // -inf (no positive in tile) is int-negative -> never beats stored >= 0
            atomicMax((int*)&out[2 + row0 + lr],      __float_as_int(mp));
            atomicMin((int*)&out[2 + NN + row0 + lr], __float_as_int(mn));
        }
    }
}

// ---------------- final deterministic reduce ----------------
__global__ void k_finish(float* __restrict__ out) {
    int t = threadIdx.x;
    float str = 0.f, sce = 0.f;
    for (int i = t; i < NN; i += 256) {
        float ap = out[2 + i];
        float an = out[2 + NN + i];
        str += fmaxf(ap - an + MARGIN_F, 0.f);
        sce += g_ce_row[i];
    }
    __shared__ float s1[256], s2[256];
    s1[t] = str; s2[t] = sce;
    __syncthreads();
    for (int o = 128; o > 0; o >>= 1) {
        if (t < o) { s1[t] += s1[t + o]; s2[t] += s2[t + o]; }
        __syncthreads();
    }
    if (t == 0) {
        out[0] = s2[0] / (float)NN;  // id_loss
        out[1] = s1[0] / (float)NN;  // tri_loss
    }
}

extern "C" void kernel_launch(void* const* d_in, const int* in_sizes, int n_in,
                              void* d_out, int out_size) {
    const float* E = (const float*)d_in[0];   // embeddings [4096, 2048]
    const float* P = (const float*)d_in[1];   // pred_ids   [4096, 8192]
    const int*   T = (const int*)d_in[2];     // target_ids [4096] (int32 — JAX x64 off)
    float* out = (float*)d_out;               // [8194]

    k_init<<<(NN + 255) / 256, 256>>>(T, out);
    k_xx<<<NN, 256>>>(E);
    k_ce<<<NN, 256>>>(P);
    dim3 g(NN / BN, NN / BM);
    k_dist<<<g, 256>>>(E, out);
    k_finish<<<1, 256>>>(out);
}

// round 4
// speedup vs baseline: 6.7532x; 6.7532x over previous
#include <cuda_runtime.h>
#include <math.h>
#include <stdint.h>

#define NN 4096
#define DD 2048
#define CC 8192
#define MARGIN_F 0.3f
#define EPSLS 0.1f

// tcgen05 is an arch-SPECIFIC (sm_103a) feature: gate it so the generic
// compute_103 PTX pass compiles a fallback instead of failing in ptxas.
#if defined(__CUDA_ARCH__) && (__CUDA_ARCH__ >= 1000) &&                        \
    (defined(__CUDA_ARCH_FEAT_SM103_ALL) || defined(__CUDA_ARCH_FEAT_SM100_ALL) || \
     defined(__CUDA_ARCH_SPECIFIC__) || defined(__CUDA_ARCH_FAMILY_SPECIFIC__))
#define TC_OK 1
#else
#define TC_OK 0
#endif

// ---------------- device scratch (no allocations allowed) ----------------
__device__ float g_xx[NN];
__device__ float g_ce_row[NN];
__device__ int   g_tgt[NN];

// ---------------- PTX helpers ----------------
__device__ __forceinline__ uint32_t smem_u32(const void* p) {
    uint32_t a;
    asm("{ .reg .u64 t; cvta.to.shared.u64 t, %1; cvt.u32.u64 %0, t; }"
        : "=r"(a) : "l"(p));
    return a;
}

#if TC_OK
__device__ __forceinline__ void mbar_init(uint32_t a, uint32_t n) {
    asm volatile("mbarrier.init.shared.b64 [%0], %1;" :: "r"(a), "r"(n) : "memory");
}
__device__ __forceinline__ void mbar_wait(uint32_t a, uint32_t ph) {
    asm volatile(
        "{\n\t"
        ".reg .pred P;\n\t"
        "WL_%=:\n\t"
        "mbarrier.try_wait.parity.acquire.cta.shared::cta.b64 P, [%0], %1, 0x989680;\n\t"
        "@P bra WD_%=;\n\t"
        "bra WL_%=;\n\t"
        "WD_%=:\n\t"
        "}" :: "r"(a), "r"(ph) : "memory");
}
__device__ __forceinline__ void tmem_alloc(uint32_t smem_dst, uint32_t ncols) {
    asm volatile("tcgen05.alloc.cta_group::1.sync.aligned.shared::cta.b32 [%0], %1;"
                 :: "r"(smem_dst), "r"(ncols) : "memory");
}
__device__ __forceinline__ void tmem_dealloc(uint32_t tmem, uint32_t ncols) {
    asm volatile("tcgen05.dealloc.cta_group::1.sync.aligned.b32 %0, %1;"
                 :: "r"(tmem), "r"(ncols));
}
__device__ __forceinline__ void tmem_relinq() {
    asm volatile("tcgen05.relinquish_alloc_permit.cta_group::1.sync.aligned;");
}
__device__ __forceinline__ void mma_commit(uint32_t mbar) {
    asm volatile("tcgen05.commit.cta_group::1.mbarrier::arrive::one.shared::cluster.b64 [%0];"
                 :: "r"(mbar) : "memory");
}
__device__ __forceinline__ void fence_async_smem() {
    asm volatile("fence.proxy.async.shared::cta;" ::: "memory");
}
__device__ __forceinline__ void tc_fence_after() {
    asm volatile("tcgen05.fence::after_thread_sync;" ::: "memory");
}
__device__ __forceinline__ void tc_fence_before() {
    asm volatile("tcgen05.fence::before_thread_sync;" ::: "memory");
}
__device__ __forceinline__ void tc_wait_ld() {
    asm volatile("tcgen05.wait::ld.sync.aligned;" ::: "memory");
}
__device__ __forceinline__ void mma_tf32_ss(uint32_t d_tmem, uint64_t a_desc,
                                            uint64_t b_desc, uint32_t idesc,
                                            uint32_t en) {
    asm volatile(
        "{\n\t"
        ".reg .pred p;\n\t"
        "setp.ne.u32 p, %5, 0;\n\t"
        "tcgen05.mma.cta_group::1.kind::tf32 [%0], %1, %2, %3, {%4, %4, %4, %4}, p;\n\t"
        "}"
        :: "r"(d_tmem), "l"(a_desc), "l"(b_desc), "r"(idesc), "r"(0u), "r"(en)
        : "memory");
}
#define LDTM_X32(r, addr)                                                        \
    asm volatile(                                                                \
        "tcgen05.ld.sync.aligned.32x32b.x32.b32 "                                \
        "{%0, %1, %2, %3, %4, %5, %6, %7, "                                      \
        " %8, %9, %10, %11, %12, %13, %14, %15, "                                \
        " %16, %17, %18, %19, %20, %21, %22, %23, "                              \
        " %24, %25, %26, %27, %28, %29, %30, %31}, [%32];"                       \
        : "=r"((r)[0]),  "=r"((r)[1]),  "=r"((r)[2]),  "=r"((r)[3]),             \
          "=r"((r)[4]),  "=r"((r)[5]),  "=r"((r)[6]),  "=r"((r)[7]),             \
          "=r"((r)[8]),  "=r"((r)[9]),  "=r"((r)[10]), "=r"((r)[11]),            \
          "=r"((r)[12]), "=r"((r)[13]), "=r"((r)[14]), "=r"((r)[15]),            \
          "=r"((r)[16]), "=r"((r)[17]), "=r"((r)[18]), "=r"((r)[19]),            \
          "=r"((r)[20]), "=r"((r)[21]), "=r"((r)[22]), "=r"((r)[23]),            \
          "=r"((r)[24]), "=r"((r)[25]), "=r"((r)[26]), "=r"((r)[27]),            \
          "=r"((r)[28]), "=r"((r)[29]), "=r"((r)[30]), "=r"((r)[31])             \
        : "r"(addr))

// SW128 K-major smem descriptor: layout=2, version=1, SBO=64, LBO=1
__device__ __forceinline__ uint64_t make_desc(uint32_t smem_addr) {
    const uint64_t base = (uint64_t(2) << 61) | (uint64_t(1) << 46) |
                          (uint64_t(64) << 32) | (uint64_t(1) << 16);
    return base | ((uint64_t)(smem_addr >> 4) & 0x3FFF);
}
// idesc: dtype=F32(1)@4, atype=TF32(2)@7, btype=TF32(2)@10, N/8=32@17, M/16=8@24
#define MMA_IDESC ((1u << 4) | (2u << 7) | (2u << 10) | (32u << 17) | (8u << 24))
#endif  // TC_OK

// ---------------- init ----------------
__global__ void k_init(const int* __restrict__ tgt, float* __restrict__ out) {
    int i = blockIdx.x * blockDim.x + threadIdx.x;
    if (i < NN) {
        int t = tgt[i];
        g_tgt[i] = min(max(t, 0), CC - 1);
        out[2 + i] = 0.0f;                       // d2_ap max-accumulator (>=0)
        ((int*)out)[2 + NN + i] = 0x7F800000;    // d2_an min-accumulator = +inf
    }
}

// ---------------- per-row sum of squares ----------------
__global__ void k_xx(const float* __restrict__ E) {
    int r = blockIdx.x;
    const float4* row = (const float4*)(E + (size_t)r * DD);
    float s = 0.f;
    for (int i = threadIdx.x; i < DD / 4; i += 256) {
        float4 v = row[i];
        s += v.x * v.x + v.y * v.y + v.z * v.z + v.w * v.w;
    }
    __shared__ float sm[256];
    sm[threadIdx.x] = s;
    __syncthreads();
    for (int o = 128; o > 0; o >>= 1) {
        if (threadIdx.x < o) sm[threadIdx.x] += sm[threadIdx.x + o];
        __syncthreads();
    }
    if (threadIdx.x == 0) g_xx[r] = sm[0];
}

// ---------------- label-smoothed CE: single global pass via smem row cache ----
__global__ void k_ce(const float* __restrict__ logits) {
    __shared__ float row_s[CC];  // 32 KB
    __shared__ float smx[256], ssm[256];
    int r = blockIdx.x;
    int t = threadIdx.x;
    const float4* row = (const float4*)(logits + (size_t)r * CC);

    float mx = -INFINITY, s = 0.f;
    for (int i = t; i < CC / 4; i += 256) {
        float4 v = row[i];
        ((float4*)row_s)[i] = v;
        mx = fmaxf(mx, fmaxf(fmaxf(v.x, v.y), fmaxf(v.z, v.w)));
        s += v.x + v.y + v.z + v.w;
    }
    smx[t] = mx; ssm[t] = s;
    __syncthreads();
    for (int o = 128; o > 0; o >>= 1) {
        if (t < o) {
            smx[t] = fmaxf(smx[t], smx[t + o]);
            ssm[t] += ssm[t + o];
        }
        __syncthreads();
    }
    mx = smx[0];
    s  = ssm[0];
    __syncthreads();

    float se = 0.f;
    for (int i = t; i < CC / 4; i += 256) {
        float4 v = ((const float4*)row_s)[i];
        se += expf(v.x - mx) + expf(v.y - mx) + expf(v.z - mx) + expf(v.w - mx);
    }
    ssm[t] = se;
    __syncthreads();
    for (int o = 128; o > 0; o >>= 1) {
        if (t < o) ssm[t] += ssm[t + o];
        __syncthreads();
    }
    if (t == 0) {
        float lse = mx + logf(ssm[0]);
        float lt  = row_s[g_tgt[r]];
        g_ce_row[r] = lse - (1.f - EPSLS) * lt - EPSLS * (s / (float)CC);
    }
}

// ---------------- Gram + batch-hard mining (on d2) ----------------
// CTA computes a 128(rows) x 256(cols) tile of D = E E^T, then per-row masked
// max/min of d2 = xx[i]+xx[j]-2G with float-as-int atomics into out.
#define DSMEM_BYTES (102400 + 1024)

__global__ void __launch_bounds__(256, 1) k_dist(const float* __restrict__ E,
                                                 float* __restrict__ out) {
    extern __shared__ char dsm_raw[];
    char* dsm = (char*)(((uintptr_t)dsm_raw + 1023) & ~(uintptr_t)1023);
    int tid = threadIdx.x;
    int row0 = blockIdx.y * 128;
    int col0 = blockIdx.x * 256;

#if TC_OK
    uint32_t sb = smem_u32(dsm);
    float* xR = (float*)(dsm + 64);
    float* xC = (float*)(dsm + 576);
    int*   tR = (int*)(dsm + 1600);
    int*   tC = (int*)(dsm + 2112);
    const uint32_t A_off[2] = {4096u, 20480u};
    const uint32_t B_off[2] = {36864u, 69632u};
    int wid = tid >> 5, lane = tid & 31;

    if (wid == 0) {
        tmem_alloc(sb + 0, 256);
        tmem_relinq();
    }
    if (tid == 0) {
        mbar_init(sb + 16, 1);
        mbar_init(sb + 24, 1);
    }
    if (tid < 128) {
        xR[tid] = g_xx[row0 + tid];
        tR[tid] = g_tgt[row0 + tid];
    }
    xC[tid] = g_xx[col0 + tid];
    tC[tid] = g_tgt[col0 + tid];
    __syncthreads();
    uint32_t tmem;
    asm volatile("ld.shared.b32 %0, [%1];" : "=r"(tmem) : "r"(sb + 0));

    uint32_t ph0 = 0, ph1 = 0;
    for (int c = 0; c < DD / 32; c++) {
        int b = c & 1;
        if (c >= 2) {
            if (b == 0) { mbar_wait(sb + 16, ph0); ph0 ^= 1; }
            else        { mbar_wait(sb + 24, ph1); ph1 ^= 1; }
        }
        int k0 = c * 32;
#pragma unroll
        for (int i = 0; i < 4; i++) {   // A: 128 rows x 32 f32 (1024 float4)
            int idx = tid + i * 256;
            int r = idx >> 3, q = idx & 7;
            float4 v = *(const float4*)(E + (size_t)(row0 + r) * DD + k0 + q * 4);
            uint32_t off = (uint32_t)(r * 128 + q * 16);
            off ^= (off >> 3) & 0x70;
            *(float4*)(dsm + A_off[b] + off) = v;
        }
#pragma unroll
        for (int i = 0; i < 8; i++) {   // B: 256 rows x 32 f32 (2048 float4)
            int idx = tid + i * 256;
            int r = idx >> 3, q = idx & 7;
            float4 v = *(const float4*)(E + (size_t)(col0 + r) * DD + k0 + q * 4);
            uint32_t off = (uint32_t)(r * 128 + q * 16);
            off ^= (off >> 3) & 0x70;
            *(float4*)(dsm + B_off[b] + off) = v;
        }
        __syncthreads();
        if (tid == 0) {
            fence_async_smem();
            uint64_t ad = make_desc(sb + A_off[b]);
            uint64_t bd = make_desc(sb + B_off[b]);
#pragma unroll
            for (int ks = 0; ks < 4; ks++)
                mma_tf32_ss(tmem, ad + ks * 2, bd + ks * 2, MMA_IDESC,
                            (c | ks) != 0);
            mma_commit(sb + 16 + b * 8);
        }
    }
    mbar_wait(sb + 16, ph0);
    mbar_wait(sb + 24, ph1);
    tc_fence_after();

    // warp w: rows (w%4)*32+lane (its TMEM subpartition), cols (w/4)*128..+127
    int r_loc = (wid & 3) * 32 + lane;
    int cbase = (wid >> 2) * 128;
    float xr = xR[r_loc];
    int   trg = tR[r_loc];
    float mp = -INFINITY, mn = INFINITY;
#pragma unroll
    for (int cb = 0; cb < 4; cb++) {
        uint32_t regs[32];
        LDTM_X32(regs, tmem + cbase + cb * 32);
        tc_wait_ld();
#pragma unroll
        for (int j = 0; j < 32; j++) {
            int cl = cbase + cb * 32 + j;
            float g  = __uint_as_float(regs[j]);
            float d2 = fmaxf(xr + xC[cl] - 2.f * g, 0.f);
            if (trg == tC[cl]) mp = fmaxf(mp, d2);
            else               mn = fminf(mn, d2);
        }
    }
    tc_fence_before();
    mp = fmaxf(mp, 0.f);
    atomicMax((int*)&out[2 + row0 + r_loc],      __float_as_int(mp));
    atomicMin((int*)&out[2 + NN + row0 + r_loc], __float_as_int(mn));

    __syncthreads();
    if (wid == 0) tmem_dealloc(tmem, 256);

#else  // ---------- generic-arch fallback: FFMA SGEMM (round-2 scheme) ----------
    float* As = (float*)(dsm);               // [16][132]
    float* Bs = (float*)(dsm + 8448);        // [16][132]
    float* xR = (float*)(dsm + 16896);       // 128
    float* xC = (float*)(dsm + 17408);       // 256
    int*   tR = (int*)(dsm + 18432);         // 128
    int*   tC = (int*)(dsm + 18944);         // 256
#define AS(k, r) As[(k) * 132 + (r)]
#define BS(k, r) Bs[(k) * 132 + (r)]

    int tx = tid & 15, ty = tid >> 4;
    if (tid < 128) {
        xR[tid] = g_xx[row0 + tid];
        tR[tid] = g_tgt[row0 + tid];
    }
    xC[tid] = g_xx[col0 + tid];
    tC[tid] = g_tgt[col0 + tid];
    __syncthreads();

    for (int h = 0; h < 2; h++) {
        int c0 = col0 + h * 128;
        float acc[8][8];
#pragma unroll
        for (int m = 0; m < 8; m++)
#pragma unroll
            for (int n = 0; n < 8; n++) acc[m][n] = 0.f;

        for (int k0 = 0; k0 < DD; k0 += 16) {
#pragma unroll
            for (int l = 0; l < 2; l++) {
                int q = tid + l * 256;
                int r = q >> 2, kq = (q & 3) << 2;
                float4 v = *(const float4*)(E + (size_t)(row0 + r) * DD + k0 + kq);
                AS(kq + 0, r) = v.x; AS(kq + 1, r) = v.y;
                AS(kq + 2, r) = v.z; AS(kq + 3, r) = v.w;
                float4 w = *(const float4*)(E + (size_t)(c0 + r) * DD + k0 + kq);
                BS(kq + 0, r) = w.x; BS(kq + 1, r) = w.y;
                BS(kq + 2, r) = w.z; BS(kq + 3, r) = w.w;
            }
            __syncthreads();
#pragma unroll
            for (int k = 0; k < 16; k++) {
                float a[8], b[8];
#pragma unroll
                for (int m = 0; m < 8; m++) a[m] = AS(k, ty + m * 16);
#pragma unroll
                for (int n = 0; n < 8; n++) b[n] = BS(k, tx + n * 16);
#pragma unroll
                for (int m = 0; m < 8; m++)
#pragma unroll
                    for (int n = 0; n < 8; n++)
                        acc[m][n] = fmaf(a[m], b[n], acc[m][n]);
            }
            __syncthreads();
        }
#pragma unroll
        for (int m = 0; m < 8; m++) {
            int   lr  = ty + m * 16;
            int   trg = tR[lr];
            float xr  = xR[lr];
            float mp = -INFINITY, mn = INFINITY;
#pragma unroll
            for (int n = 0; n < 8; n++) {
                int   lc = h * 128 + tx + n * 16;
                float d2 = fmaxf(xr + xC[lc] - 2.f * acc[m][n], 0.f);
                if (trg == tC[lc]) mp = fmaxf(mp, d2);
                else               mn = fminf(mn, d2);
            }
#pragma unroll
            for (int o = 8; o > 0; o >>= 1) {
                mp = fmaxf(mp, __shfl_xor_sync(0xFFFFFFFF, mp, o));
                mn = fminf(mn, __shfl_xor_sync(0xFFFFFFFF, mn, o));
            }
            if (tx == 0) {
                atomicMax((int*)&out[2 + row0 + lr],      __float_as_int(mp));
                atomicMin((int*)&out[2 + NN + row0 + lr], __float_as_int(mn));
            }
        }
        __syncthreads();
    }
#undef AS
#undef BS
#endif
}

// ---------------- final deterministic reduce (+ d2 -> dist) ----------------
__global__ void k_finish(float* __restrict__ out) {
    int t = threadIdx.x;
    float str = 0.f, sce = 0.f;
    for (int i = t; i < NN; i += 256) {
        float ap = sqrtf(fmaxf(out[2 + i],      1e-12f));
        float an = sqrtf(fmaxf(out[2 + NN + i], 1e-12f));
        out[2 + i]      = ap;
        out[2 + NN + i] = an;
        str += fmaxf(ap - an + MARGIN_F, 0.f);
        sce += g_ce_row[i];
    }
    __shared__ float s1[256], s2[256];
    s1[t] = str; s2[t] = sce;
    __syncthreads();
    for (int o = 128; o > 0; o >>= 1) {
        if (t < o) { s1[t] += s1[t + o]; s2[t] += s2[t + o]; }
        __syncthreads();
    }
    if (t == 0) {
        out[0] = s2[0] / (float)NN;  // id_loss
        out[1] = s1[0] / (float)NN;  // tri_loss
    }
}

extern "C" void kernel_launch(void* const* d_in, const int* in_sizes, int n_in,
                              void* d_out, int out_size) {
    const float* E = (const float*)d_in[0];   // embeddings [4096, 2048]
    const float* P = (const float*)d_in[1];   // pred_ids   [4096, 8192]
    const int*   T = (const int*)d_in[2];     // target_ids [4096] int32
    float* out = (float*)d_out;               // [8194]

    cudaFuncSetAttribute(k_dist, cudaFuncAttributeMaxDynamicSharedMemorySize,
                         DSMEM_BYTES);

    k_init<<<(NN + 255) / 256, 256>>>(T, out);
    k_xx<<<NN, 256>>>(E);
    dim3 g(NN / 256, NN / 128);
    k_dist<<<g, 256, DSMEM_BYTES>>>(E, out);
    k_ce<<<NN, 256>>>(P);
    k_finish<<<1, 256>>>(out);
}

// round 5
// speedup vs baseline: 9.5645x; 1.4163x over previous
#include <cuda_runtime.h>
#include <math.h>
#include <stdint.h>

#define NN 4096
#define DD 2048
#define CC 8192
#define MARGIN_F 0.3f
#define EPSLS 0.1f

// tcgen05 is arch-SPECIFIC (sm_103a): gate so the generic compute_103 PTX
// pass compiles a fallback instead of failing ptxas.
#if defined(__CUDA_ARCH__) && (__CUDA_ARCH__ >= 1000) &&                        \
    (defined(__CUDA_ARCH_FEAT_SM103_ALL) || defined(__CUDA_ARCH_FEAT_SM100_ALL) || \
     defined(__CUDA_ARCH_SPECIFIC__) || defined(__CUDA_ARCH_FAMILY_SPECIFIC__))
#define TC_OK 1
#else
#define TC_OK 0
#endif

// ---------------- device scratch (no allocations allowed) ----------------
__device__ float g_xx[NN];
__device__ float g_ce_row[NN];
__device__ int   g_tgt[NN];

// ---------------- PTX helpers ----------------
__device__ __forceinline__ uint32_t smem_u32(const void* p) {
    uint32_t a;
    asm("{ .reg .u64 t; cvta.to.shared.u64 t, %1; cvt.u32.u64 %0, t; }"
        : "=r"(a) : "l"(p));
    return a;
}

#if TC_OK
__device__ __forceinline__ void mbar_init(uint32_t a, uint32_t n) {
    asm volatile("mbarrier.init.shared.b64 [%0], %1;" :: "r"(a), "r"(n) : "memory");
}
__device__ __forceinline__ void mbar_wait(uint32_t a, uint32_t ph) {
    asm volatile(
        "{\n\t"
        ".reg .pred P;\n\t"
        "WL_%=:\n\t"
        "mbarrier.try_wait.parity.acquire.cta.shared::cta.b64 P, [%0], %1, 0x989680;\n\t"
        "@P bra WD_%=;\n\t"
        "bra WL_%=;\n\t"
        "WD_%=:\n\t"
        "}" :: "r"(a), "r"(ph) : "memory");
}
__device__ __forceinline__ void tmem_alloc(uint32_t smem_dst, uint32_t ncols) {
    asm volatile("tcgen05.alloc.cta_group::1.sync.aligned.shared::cta.b32 [%0], %1;"
                 :: "r"(smem_dst), "r"(ncols) : "memory");
}
__device__ __forceinline__ void tmem_dealloc(uint32_t tmem, uint32_t ncols) {
    asm volatile("tcgen05.dealloc.cta_group::1.sync.aligned.b32 %0, %1;"
                 :: "r"(tmem), "r"(ncols));
}
__device__ __forceinline__ void tmem_relinq() {
    asm volatile("tcgen05.relinquish_alloc_permit.cta_group::1.sync.aligned;");
}
__device__ __forceinline__ void mma_commit(uint32_t mbar) {
    asm volatile("tcgen05.commit.cta_group::1.mbarrier::arrive::one.shared::cluster.b64 [%0];"
                 :: "r"(mbar) : "memory");
}
__device__ __forceinline__ void fence_async_smem() {
    asm volatile("fence.proxy.async.shared::cta;" ::: "memory");
}
__device__ __forceinline__ void tc_fence_after() {
    asm volatile("tcgen05.fence::after_thread_sync;" ::: "memory");
}
__device__ __forceinline__ void tc_fence_before() {
    asm volatile("tcgen05.fence::before_thread_sync;" ::: "memory");
}
__device__ __forceinline__ void tc_wait_ld() {
    asm volatile("tcgen05.wait::ld.sync.aligned;" ::: "memory");
}
__device__ __forceinline__ void mma_tf32_ss(uint32_t d_tmem, uint64_t a_desc,
                                            uint64_t b_desc, uint32_t idesc,
                                            uint32_t en) {
    asm volatile(
        "{\n\t"
        ".reg .pred p;\n\t"
        "setp.ne.u32 p, %5, 0;\n\t"
        "tcgen05.mma.cta_group::1.kind::tf32 [%0], %1, %2, %3, {%4, %4, %4, %4}, p;\n\t"
        "}"
        :: "r"(d_tmem), "l"(a_desc), "l"(b_desc), "r"(idesc), "r"(0u), "r"(en)
        : "memory");
}
#define LDTM_X32(r, addr)                                                        \
    asm volatile(                                                                \
        "tcgen05.ld.sync.aligned.32x32b.x32.b32 "                                \
        "{%0, %1, %2, %3, %4, %5, %6, %7, "                                      \
        " %8, %9, %10, %11, %12, %13, %14, %15, "                                \
        " %16, %17, %18, %19, %20, %21, %22, %23, "                              \
        " %24, %25, %26, %27, %28, %29, %30, %31}, [%32];"                       \
        : "=r"((r)[0]),  "=r"((r)[1]),  "=r"((r)[2]),  "=r"((r)[3]),             \
          "=r"((r)[4]),  "=r"((r)[5]),  "=r"((r)[6]),  "=r"((r)[7]),             \
          "=r"((r)[8]),  "=r"((r)[9]),  "=r"((r)[10]), "=r"((r)[11]),            \
          "=r"((r)[12]), "=r"((r)[13]), "=r"((r)[14]), "=r"((r)[15]),            \
          "=r"((r)[16]), "=r"((r)[17]), "=r"((r)[18]), "=r"((r)[19]),            \
          "=r"((r)[20]), "=r"((r)[21]), "=r"((r)[22]), "=r"((r)[23]),            \
          "=r"((r)[24]), "=r"((r)[25]), "=r"((r)[26]), "=r"((r)[27]),            \
          "=r"((r)[28]), "=r"((r)[29]), "=r"((r)[30]), "=r"((r)[31])             \
        : "r"(addr))

// SW128 K-major smem descriptor: layout=2, version=1, SBO=64, LBO=1
__device__ __forceinline__ uint64_t make_desc(uint32_t smem_addr) {
    const uint64_t base = (uint64_t(2) << 61) | (uint64_t(1) << 46) |
                          (uint64_t(64) << 32) | (uint64_t(1) << 16);
    return base | ((uint64_t)(smem_addr >> 4) & 0x3FFF);
}
// idesc: dtype=F32(1)@4, atype=TF32(2)@7, btype=TF32(2)@10, N/8=32@17, M/16=8@24
#define MMA_IDESC ((1u << 4) | (2u << 7) | (2u << 10) | (32u << 17) | (8u << 24))
#endif  // TC_OK

// ---------------- init ----------------
__global__ void k_init(const int* __restrict__ tgt, float* __restrict__ out) {
    int i = blockIdx.x * blockDim.x + threadIdx.x;
    if (i < NN) {
        int t = tgt[i];
        g_tgt[i] = min(max(t, 0), CC - 1);
        out[2 + i] = 0.0f;                       // d2_ap max-accumulator (>=0)
        ((int*)out)[2 + NN + i] = 0x7F800000;    // d2_an min-accumulator = +inf
    }
}

// ---------------- per-row sum of squares ----------------
__global__ void k_xx(const float* __restrict__ E) {
    int r = blockIdx.x;
    const float4* row = (const float4*)(E + (size_t)r * DD);
    float s = 0.f;
    for (int i = threadIdx.x; i < DD / 4; i += 256) {
        float4 v = row[i];
        s += v.x * v.x + v.y * v.y + v.z * v.z + v.w * v.w;
    }
    __shared__ float sm[256];
    sm[threadIdx.x] = s;
    __syncthreads();
    for (int o = 128; o > 0; o >>= 1) {
        if (threadIdx.x < o) sm[threadIdx.x] += sm[threadIdx.x + o];
        __syncthreads();
    }
    if (threadIdx.x == 0) g_xx[r] = sm[0];
}

// ---------------- label-smoothed CE: register-resident, single global pass ----
__global__ void __launch_bounds__(256) k_ce(const float* __restrict__ logits) {
    int r = blockIdx.x;
    int t = threadIdx.x;
    int lane = t & 31, wrp = t >> 5;
    const float4* row = (const float4*)(logits + (size_t)r * CC);

    float4 v[8];
    float mx = -INFINITY, s = 0.f;
#pragma unroll
    for (int i = 0; i < 8; i++) {
        v[i] = row[t + i * 256];
        mx = fmaxf(mx, fmaxf(fmaxf(v[i].x, v[i].y), fmaxf(v[i].z, v[i].w)));
        s += v[i].x + v[i].y + v[i].z + v[i].w;
    }
    __shared__ float smx[8], ssm[8], sse[8];
#pragma unroll
    for (int o = 16; o > 0; o >>= 1) {
        mx = fmaxf(mx, __shfl_xor_sync(0xFFFFFFFF, mx, o));
        s += __shfl_xor_sync(0xFFFFFFFF, s, o);
    }
    if (lane == 0) { smx[wrp] = mx; ssm[wrp] = s; }
    __syncthreads();
    if (wrp == 0) {
        float m2 = (lane < 8) ? smx[lane] : -INFINITY;
        float s2 = (lane < 8) ? ssm[lane] : 0.f;
#pragma unroll
        for (int o = 4; o > 0; o >>= 1) {
            m2 = fmaxf(m2, __shfl_xor_sync(0xFFFFFFFF, m2, o));
            s2 += __shfl_xor_sync(0xFFFFFFFF, s2, o);
        }
        if (lane == 0) { smx[0] = m2; ssm[0] = s2; }
    }
    __syncthreads();
    mx = smx[0];
    s  = ssm[0];

    float se = 0.f;
#pragma unroll
    for (int i = 0; i < 8; i++) {
        se += __expf(v[i].x - mx) + __expf(v[i].y - mx) +
              __expf(v[i].z - mx) + __expf(v[i].w - mx);
    }
#pragma unroll
    for (int o = 16; o > 0; o >>= 1) se += __shfl_xor_sync(0xFFFFFFFF, se, o);
    if (lane == 0) sse[wrp] = se;
    __syncthreads();
    if (t == 0) {
        float tot = 0.f;
#pragma unroll
        for (int i = 0; i < 8; i++) tot += sse[i];
        float lse = mx + logf(tot);
        float lt  = logits[(size_t)r * CC + g_tgt[r]];
        g_ce_row[r] = lse - (1.f - EPSLS) * lt - EPSLS * (s / (float)CC);
    }
}

// ---------------- Gram + batch-hard mining (on d2) ----------------
// CTA computes a 256(rows) x 256(cols) tile using the FULL 512-col TMEM:
// rows 0-127 -> TMEM cols [0,256), rows 128-255 -> TMEM cols [256,512).
// K chunks of 32, double-buffered SMEM, 8 tf32 MMAs (2 halves x 4 k-steps).
#define DSMEM_BYTES (139264 + 1024)

__global__ void __launch_bounds__(512, 1) k_dist(const float* __restrict__ E,
                                                 float* __restrict__ out) {
    extern __shared__ char dsm_raw[];
    char* dsm = (char*)(((uintptr_t)dsm_raw + 1023) & ~(uintptr_t)1023);
    int tid = threadIdx.x;
    int row0 = blockIdx.y * 256;
    int col0 = blockIdx.x * 256;

#if TC_OK
    uint32_t sb = smem_u32(dsm);
    float* xR = (float*)(dsm + 64);      // 256
    float* xC = (float*)(dsm + 1088);    // 256
    int*   tR = (int*)(dsm + 2112);      // 256
    int*   tC = (int*)(dsm + 3136);      // 256
    const uint32_t A_off[2] = {8192u, 40960u};     // 32KB each (256 rows x 128B)
    const uint32_t B_off[2] = {73728u, 106496u};   // 32KB each
    int wid = tid >> 5, lane = tid & 31;

    if (wid == 0) {
        tmem_alloc(sb + 0, 512);
        tmem_relinq();
    }
    if (tid == 0) {
        mbar_init(sb + 16, 1);
        mbar_init(sb + 24, 1);
    }
    if (tid < 256) {
        xR[tid] = g_xx[row0 + tid];
        tR[tid] = g_tgt[row0 + tid];
    } else {
        int j = tid - 256;
        xC[j] = g_xx[col0 + j];
        tC[j] = g_tgt[col0 + j];
    }
    __syncthreads();
    uint32_t tmem;
    asm volatile("ld.shared.b32 %0, [%1];" : "=r"(tmem) : "r"(sb + 0));

    uint32_t ph0 = 0, ph1 = 0;
    for (int c = 0; c < DD / 32; c++) {
        int b = c & 1;
        if (c >= 2) {
            if (b == 0) { mbar_wait(sb + 16, ph0); ph0 ^= 1; }
            else        { mbar_wait(sb + 24, ph1); ph1 ^= 1; }
        }
        int k0 = c * 32;
#pragma unroll
        for (int i = 0; i < 4; i++) {   // A: 256 rows x 32 f32 (2048 float4)
            int idx = tid + i * 512;
            int r = idx >> 3, q = idx & 7;
            float4 v = *(const float4*)(E + (size_t)(row0 + r) * DD + k0 + q * 4);
            uint32_t off = (uint32_t)(r * 128 + q * 16);
            off ^= (off >> 3) & 0x70;
            *(float4*)(dsm + A_off[b] + off) = v;
        }
#pragma unroll
        for (int i = 0; i < 4; i++) {   // B: 256 rows x 32 f32 (2048 float4)
            int idx = tid + i * 512;
            int r = idx >> 3, q = idx & 7;
            float4 v = *(const float4*)(E + (size_t)(col0 + r) * DD + k0 + q * 4);
            uint32_t off = (uint32_t)(r * 128 + q * 16);
            off ^= (off >> 3) & 0x70;
            *(float4*)(dsm + B_off[b] + off) = v;
        }
        __syncthreads();
        if (tid == 0) {
            fence_async_smem();
            uint64_t a0 = make_desc(sb + A_off[b]);           // rows 0-127
            uint64_t a1 = make_desc(sb + A_off[b] + 16384);   // rows 128-255
            uint64_t bd = make_desc(sb + B_off[b]);
            uint32_t en = (c != 0);
#pragma unroll
            for (int ks = 0; ks < 4; ks++) {
                uint32_t e = en | (ks != 0);
                mma_tf32_ss(tmem,       a0 + ks * 2, bd + ks * 2, MMA_IDESC, e);
                mma_tf32_ss(tmem + 256, a1 + ks * 2, bd + ks * 2, MMA_IDESC, e);
            }
            mma_commit(sb + 16 + b * 8);
        }
    }
    mbar_wait(sb + 16, ph0);
    mbar_wait(sb + 24, ph1);
    tc_fence_after();

    // Epilogue: warp w -> subpartition s=w&3 (TMEM lanes s*32+lane),
    // col-group g=w>>2 (64 cols), both row halves h.
    int s_ = wid & 3, g_ = wid >> 2;
#pragma unroll
    for (int h = 0; h < 2; h++) {
        int r_tile = h * 128 + s_ * 32 + lane;
        float xr = xR[r_tile];
        int   trg = tR[r_tile];
        float mp = -INFINITY, mn = INFINITY;
#pragma unroll
        for (int cb = 0; cb < 2; cb++) {
            uint32_t regs[32];
            LDTM_X32(regs, tmem + h * 256 + g_ * 64 + cb * 32);
            tc_wait_ld();
#pragma unroll
            for (int j = 0; j < 32; j++) {
                int cl = g_ * 64 + cb * 32 + j;
                float g  = __uint_as_float(regs[j]);
                float d2 = fmaxf(xr + xC[cl] - 2.f * g, 0.f);
                if (trg == tC[cl]) mp = fmaxf(mp, d2);
                else               mn = fminf(mn, d2);
            }
        }
        mp = fmaxf(mp, 0.f);
        atomicMax((int*)&out[2 + row0 + r_tile],      __float_as_int(mp));
        atomicMin((int*)&out[2 + NN + row0 + r_tile], __float_as_int(mn));
    }
    tc_fence_before();

    __syncthreads();
    if (wid == 0) tmem_dealloc(tmem, 512);

#else  // ---------- generic-arch fallback: FFMA SGEMM ----------
    float* As = (float*)(dsm);               // [16][264]
    float* Bs = (float*)(dsm + 16896);       // [16][264]
    float* xR = (float*)(dsm + 33792);       // 256
    float* xC = (float*)(dsm + 34816);       // 256
    int*   tR = (int*)(dsm + 35840);         // 256
    int*   tC = (int*)(dsm + 36864);         // 256
#define AS(k, r) As[(k) * 264 + (r)]
#define BS(k, r) Bs[(k) * 264 + (r)]

    int tx = tid & 15, ty = tid >> 4;  // ty 0..31
    if (tid < 256) {
        xR[tid] = g_xx[row0 + tid];
        tR[tid] = g_tgt[row0 + tid];
    } else {
        int j = tid - 256;
        xC[j] = g_xx[col0 + j];
        tC[j] = g_tgt[col0 + j];
    }
    __syncthreads();

    for (int h = 0; h < 2; h++) {
        int c0 = col0 + h * 128;
        float acc[8][8];
#pragma unroll
        for (int m = 0; m < 8; m++)
#pragma unroll
            for (int n = 0; n < 8; n++) acc[m][n] = 0.f;

        for (int k0 = 0; k0 < DD; k0 += 16) {
            // A: 256 rows x 16 = 1024 float4 (2 iters); B: 128 rows x 16 = 512 f4
#pragma unroll
            for (int l = 0; l < 2; l++) {
                int q = tid + l * 512;
                int r = q >> 2, kq = (q & 3) << 2;
                float4 v = *(const float4*)(E + (size_t)(row0 + r) * DD + k0 + kq);
                AS(kq + 0, r) = v.x; AS(kq + 1, r) = v.y;
                AS(kq + 2, r) = v.z; AS(kq + 3, r) = v.w;
            }
            if (tid < 512) {
                int q = tid;
                int r = q >> 2, kq = (q & 3) << 2;
                float4 w = *(const float4*)(E + (size_t)(c0 + r) * DD + k0 + kq);
                BS(kq + 0, r) = w.x; BS(kq + 1, r) = w.y;
                BS(kq + 2, r) = w.z; BS(kq + 3, r) = w.w;
            }
            __syncthreads();
#pragma unroll
            for (int k = 0; k < 16; k++) {
                float a[8], b[8];
#pragma unroll
                for (int m = 0; m < 8; m++) a[m] = AS(k, ty + m * 32);
#pragma unroll
                for (int n = 0; n < 8; n++) b[n] = BS(k, tx + n * 16);
#pragma unroll
                for (int m = 0; m < 8; m++)
#pragma unroll
                    for (int n = 0; n < 8; n++)
                        acc[m][n] = fmaf(a[m], b[n], acc[m][n]);
            }
            __syncthreads();
        }
#pragma unroll
        for (int m = 0; m < 8; m++) {
            int   lr  = ty + m * 32;
            int   trg = tR[lr];
            float xr  = xR[lr];
            float mp = -INFINITY, mn = INFINITY;
#pragma unroll
            for (int n = 0; n < 8; n++) {
                int   lc = h * 128 + tx + n * 16;
                float d2 = fmaxf(xr + xC[lc] - 2.f * acc[m][n], 0.f);
                if (trg == tC[lc]) mp = fmaxf(mp, d2);
                else               mn = fminf(mn, d2);
            }
#pragma unroll
            for (int o = 8; o > 0; o >>= 1) {
                mp = fmaxf(mp, __shfl_xor_sync(0xFFFFFFFF, mp, o));
                mn = fminf(mn, __shfl_xor_sync(0xFFFFFFFF, mn, o));
            }
            if (tx == 0) {
                atomicMax((int*)&out[2 + row0 + lr],      __float_as_int(mp));
                atomicMin((int*)&out[2 + NN + row0 + lr], __float_as_int(mn));
            }
        }
        __syncthreads();
    }
#undef AS
#undef BS
#endif
}

// ---------------- final deterministic reduce (+ d2 -> dist) ----------------
__global__ void k_finish(float* __restrict__ out) {
    int t = threadIdx.x;
    float str = 0.f, sce = 0.f;
    for (int i = t; i < NN; i += 256) {
        float ap = sqrtf(fmaxf(out[2 + i],      1e-12f));
        float an = sqrtf(fmaxf(out[2 + NN + i], 1e-12f));
        out[2 + i]      = ap;
        out[2 + NN + i] = an;
        str += fmaxf(ap - an + MARGIN_F, 0.f);
        sce += g_ce_row[i];
    }
    __shared__ float s1[256], s2[256];
    s1[t] = str; s2[t] = sce;
    __syncthreads();
    for (int o = 128; o > 0; o >>= 1) {
        if (t < o) { s1[t] += s1[t + o]; s2[t] += s2[t + o]; }
        __syncthreads();
    }
    if (t == 0) {
        out[0] = s2[0] / (float)NN;  // id_loss
        out[1] = s1[0] / (float)NN;  // tri_loss
    }
}

extern "C" void kernel_launch(void* const* d_in, const int* in_sizes, int n_in,
                              void* d_out, int out_size) {
    const float* E = (const float*)d_in[0];   // embeddings [4096, 2048]
    const float* P = (const float*)d_in[1];   // pred_ids   [4096, 8192]
    const int*   T = (const int*)d_in[2];     // target_ids [4096] int32
    float* out = (float*)d_out;               // [8194]

    cudaFuncSetAttribute(k_dist, cudaFuncAttributeMaxDynamicSharedMemorySize,
                         DSMEM_BYTES);

    k_init<<<(NN + 255) / 256, 256>>>(T, out);
    k_xx<<<NN, 256>>>(E);
    dim3 g(NN / 256, NN / 256);
    k_dist<<<g, 512, DSMEM_BYTES>>>(E, out);
    k_ce<<<NN, 256>>>(P);
    k_finish<<<1, 256>>>(out);
}

// round 6
// speedup vs baseline: 12.7923x; 1.3375x over previous
#include <cuda_runtime.h>
#include <math.h>
#include <stdint.h>

#define NN 4096
#define DD 2048
#define CC 8192
#define MARGIN_F 0.3f
#define EPSLS 0.1f

#if defined(__CUDA_ARCH__) && (__CUDA_ARCH__ >= 1000) &&                        \
    (defined(__CUDA_ARCH_FEAT_SM103_ALL) || defined(__CUDA_ARCH_FEAT_SM100_ALL) || \
     defined(__CUDA_ARCH_SPECIFIC__) || defined(__CUDA_ARCH_FAMILY_SPECIFIC__))
#define TC_OK 1
#else
#define TC_OK 0
#endif

// ---------------- device scratch ----------------
__device__ float g_xx[NN];
__device__ float g_ce_row[NN];
__device__ int   g_tgt[NN];

// ---------------- PTX helpers ----------------
__device__ __forceinline__ uint32_t smem_u32(const void* p) {
    uint32_t a;
    asm("{ .reg .u64 t; cvta.to.shared.u64 t, %1; cvt.u32.u64 %0, t; }"
        : "=r"(a) : "l"(p));
    return a;
}

#if TC_OK
__device__ __forceinline__ void mbar_init(uint32_t a, uint32_t n) {
    asm volatile("mbarrier.init.shared.b64 [%0], %1;" :: "r"(a), "r"(n) : "memory");
}
__device__ __forceinline__ void mbar_wait(uint32_t a, uint32_t ph) {
    asm volatile(
        "{\n\t"
        ".reg .pred P;\n\t"
        "WL_%=:\n\t"
        "mbarrier.try_wait.parity.acquire.cta.shared::cta.b64 P, [%0], %1, 0x989680;\n\t"
        "@P bra WD_%=;\n\t"
        "bra WL_%=;\n\t"
        "WD_%=:\n\t"
        "}" :: "r"(a), "r"(ph) : "memory");
}
__device__ __forceinline__ void tmem_alloc(uint32_t smem_dst, uint32_t ncols) {
    asm volatile("tcgen05.alloc.cta_group::1.sync.aligned.shared::cta.b32 [%0], %1;"
                 :: "r"(smem_dst), "r"(ncols) : "memory");
}
__device__ __forceinline__ void tmem_dealloc(uint32_t tmem, uint32_t ncols) {
    asm volatile("tcgen05.dealloc.cta_group::1.sync.aligned.b32 %0, %1;"
                 :: "r"(tmem), "r"(ncols));
}
__device__ __forceinline__ void tmem_relinq() {
    asm volatile("tcgen05.relinquish_alloc_permit.cta_group::1.sync.aligned;");
}
__device__ __forceinline__ void mma_commit(uint32_t mbar) {
    asm volatile("tcgen05.commit.cta_group::1.mbarrier::arrive::one.shared::cluster.b64 [%0];"
                 :: "r"(mbar) : "memory");
}
__device__ __forceinline__ void fence_async_smem() {
    asm volatile("fence.proxy.async.shared::cta;" ::: "memory");
}
__device__ __forceinline__ void tc_fence_after() {
    asm volatile("tcgen05.fence::after_thread_sync;" ::: "memory");
}
__device__ __forceinline__ void tc_fence_before() {
    asm volatile("tcgen05.fence::before_thread_sync;" ::: "memory");
}
__device__ __forceinline__ void tc_wait_ld() {
    asm volatile("tcgen05.wait::ld.sync.aligned;" ::: "memory");
}
__device__ __forceinline__ void mma_tf32_ss(uint32_t d_tmem, uint64_t a_desc,
                                            uint64_t b_desc, uint32_t idesc,
                                            uint32_t en) {
    asm volatile(
        "{\n\t"
        ".reg .pred p;\n\t"
        "setp.ne.u32 p, %5, 0;\n\t"
        "tcgen05.mma.cta_group::1.kind::tf32 [%0], %1, %2, %3, {%4, %4, %4, %4}, p;\n\t"
        "}"
        :: "r"(d_tmem), "l"(a_desc), "l"(b_desc), "r"(idesc), "r"(0u), "r"(en)
        : "memory");
}
#define LDTM_X32(r, addr)                                                        \
    asm volatile(                                                                \
        "tcgen05.ld.sync.aligned.32x32b.x32.b32 "                                \
        "{%0, %1, %2, %3, %4, %5, %6, %7, "                                      \
        " %8, %9, %10, %11, %12, %13, %14, %15, "                                \
        " %16, %17, %18, %19, %20, %21, %22, %23, "                              \
        " %24, %25, %26, %27, %28, %29, %30, %31}, [%32];"                       \
        : "=r"((r)[0]),  "=r"((r)[1]),  "=r"((r)[2]),  "=r"((r)[3]),             \
          "=r"((r)[4]),  "=r"((r)[5]),  "=r"((r)[6]),  "=r"((r)[7]),             \
          "=r"((r)[8]),  "=r"((r)[9]),  "=r"((r)[10]), "=r"((r)[11]),            \
          "=r"((r)[12]), "=r"((r)[13]), "=r"((r)[14]), "=r"((r)[15]),            \
          "=r"((r)[16]), "=r"((r)[17]), "=r"((r)[18]), "=r"((r)[19]),            \
          "=r"((r)[20]), "=r"((r)[21]), "=r"((r)[22]), "=r"((r)[23]),            \
          "=r"((r)[24]), "=r"((r)[25]), "=r"((r)[26]), "=r"((r)[27]),            \
          "=r"((r)[28]), "=r"((r)[29]), "=r"((r)[30]), "=r"((r)[31])             \
        : "r"(addr))

// SW128 K-major smem descriptor: layout=2, version=1, SBO=64, LBO=1
__device__ __forceinline__ uint64_t make_desc(uint32_t smem_addr) {
    const uint64_t base = (uint64_t(2) << 61) | (uint64_t(1) << 46) |
                          (uint64_t(64) << 32) | (uint64_t(1) << 16);
    return base | ((uint64_t)(smem_addr >> 4) & 0x3FFF);
}
#define MMA_IDESC ((1u << 4) | (2u << 7) | (2u << 10) | (32u << 17) | (8u << 24))
#endif  // TC_OK

// ---------------- init ----------------
__global__ void k_init(const int* __restrict__ tgt, float* __restrict__ out) {
    int i = blockIdx.x * blockDim.x + threadIdx.x;
    if (i < NN) {
        int t = tgt[i];
        g_tgt[i] = min(max(t, 0), CC - 1);
        out[2 + i] = 0.0f;                       // d2_ap max-acc (>=0)
        ((int*)out)[2 + NN + i] = 0x7F800000;    // d2_an min-acc = +inf
    }
}

// ---------------- per-row sum of squares ----------------
__global__ void k_xx(const float* __restrict__ E) {
    int r = blockIdx.x;
    const float4* row = (const float4*)(E + (size_t)r * DD);
    float s = 0.f;
    for (int i = threadIdx.x; i < DD / 4; i += 256) {
        float4 v = row[i];
        s += v.x * v.x + v.y * v.y + v.z * v.z + v.w * v.w;
    }
    __shared__ float sm[256];
    sm[threadIdx.x] = s;
    __syncthreads();
    for (int o = 128; o > 0; o >>= 1) {
        if (threadIdx.x < o) sm[threadIdx.x] += sm[threadIdx.x + o];
        __syncthreads();
    }
    if (threadIdx.x == 0) g_xx[r] = sm[0];
}

// ---------------- label-smoothed CE: register-resident, single pass ----------
__global__ void __launch_bounds__(256) k_ce(const float* __restrict__ logits) {
    int r = blockIdx.x;
    int t = threadIdx.x;
    int lane = t & 31, wrp = t >> 5;
    const float4* row = (const float4*)(logits + (size_t)r * CC);

    float4 v[8];
    float mx = -INFINITY, s = 0.f;
#pragma unroll
    for (int i = 0; i < 8; i++) {
        v[i] = row[t + i * 256];
        mx = fmaxf(mx, fmaxf(fmaxf(v[i].x, v[i].y), fmaxf(v[i].z, v[i].w)));
        s += v[i].x + v[i].y + v[i].z + v[i].w;
    }
    __shared__ float smx[8], ssm[8], sse[8];
#pragma unroll
    for (int o = 16; o > 0; o >>= 1) {
        mx = fmaxf(mx, __shfl_xor_sync(0xFFFFFFFF, mx, o));
        s += __shfl_xor_sync(0xFFFFFFFF, s, o);
    }
    if (lane == 0) { smx[wrp] = mx; ssm[wrp] = s; }
    __syncthreads();
    if (wrp == 0) {
        float m2 = (lane < 8) ? smx[lane] : -INFINITY;
        float s2 = (lane < 8) ? ssm[lane] : 0.f;
#pragma unroll
        for (int o = 4; o > 0; o >>= 1) {
            m2 = fmaxf(m2, __shfl_xor_sync(0xFFFFFFFF, m2, o));
            s2 += __shfl_xor_sync(0xFFFFFFFF, s2, o);
        }
        if (lane == 0) { smx[0] = m2; ssm[0] = s2; }
    }
    __syncthreads();
    mx = smx[0];
    s  = ssm[0];

    float se = 0.f;
#pragma unroll
    for (int i = 0; i < 8; i++) {
        se += __expf(v[i].x - mx) + __expf(v[i].y - mx) +
              __expf(v[i].z - mx) + __expf(v[i].w - mx);
    }
#pragma unroll
    for (int o = 16; o > 0; o >>= 1) se += __shfl_xor_sync(0xFFFFFFFF, se, o);
    if (lane == 0) sse[wrp] = se;
    __syncthreads();
    if (t == 0) {
        float tot = 0.f;
#pragma unroll
        for (int i = 0; i < 8; i++) tot += sse[i];
        float lse = mx + logf(tot);
        float lt  = logits[(size_t)r * CC + g_tgt[r]];
        g_ce_row[r] = lse - (1.f - EPSLS) * lt - EPSLS * (s / (float)CC);
    }
}

// ---------------- symmetric Gram + batch-hard mining (on d2) ----------------
// Upper-triangular tiling: 136 CTAs, tile (bi,bj) with bi<=bj, 256x256 each.
// Off-diagonal tiles mine BOTH directions (rows via per-lane reduce, cols via
// shfl reduce), merged in smem then one global atomic per row/col.
#define DSMEM_BYTES 145408

__global__ void __launch_bounds__(512, 1) k_dist(const float* __restrict__ E,
                                                 float* __restrict__ out) {
    extern __shared__ char dsm_raw[];
    char* dsm = (char*)(((uintptr_t)dsm_raw + 1023) & ~(uintptr_t)1023);
    int tid = threadIdx.x;

    // triangle mapping: bid -> (bi, bj), bi<=bj over 16x16 tiles
    int bi = 0, rem = blockIdx.x;
#pragma unroll 1
    while (rem >= 16 - bi) { rem -= 16 - bi; bi++; }
    int bj = bi + rem;
    int row0 = bi * 256, col0 = bj * 256;
    bool offdiag = (bi != bj);

#if TC_OK
    uint32_t sb = smem_u32(dsm);
    float* xR = (float*)(dsm + 64);      // 256
    float* xC = (float*)(dsm + 1088);    // 256
    int*   tR = (int*)(dsm + 2112);      // 256
    int*   tC = (int*)(dsm + 3136);      // 256
    int* rowap = (int*)(dsm + 4160);     // 256
    int* rowan = (int*)(dsm + 5184);
    int* colap = (int*)(dsm + 6208);
    int* colan = (int*)(dsm + 7232);
    const uint32_t A_off[2] = {12288u, 45056u};
    const uint32_t B_off[2] = {77824u, 110592u};
    int wid = tid >> 5, lane = tid & 31;

    if (wid == 0) {
        tmem_alloc(sb + 0, 512);
        tmem_relinq();
    }
    if (tid == 0) {
        mbar_init(sb + 16, 1);
        mbar_init(sb + 24, 1);
    }
    if (tid < 256) {
        xR[tid] = g_xx[row0 + tid];
        tR[tid] = g_tgt[row0 + tid];
        rowap[tid] = 0;
        colap[tid] = 0;
    } else {
        int j = tid - 256;
        xC[j] = g_xx[col0 + j];
        tC[j] = g_tgt[col0 + j];
        rowan[j] = 0x7F800000;
        colan[j] = 0x7F800000;
    }
    __syncthreads();
    uint32_t tmem;
    asm volatile("ld.shared.b32 %0, [%1];" : "=r"(tmem) : "r"(sb + 0));

    uint32_t ph0 = 0, ph1 = 0;
    for (int c = 0; c < DD / 32; c++) {
        int b = c & 1;
        if (c >= 2) {
            if (b == 0) { mbar_wait(sb + 16, ph0); ph0 ^= 1; }
            else        { mbar_wait(sb + 24, ph1); ph1 ^= 1; }
        }
        int k0 = c * 32;
#pragma unroll
        for (int i = 0; i < 4; i++) {   // A: 256 rows x 32 f32
            int idx = tid + i * 512;
            int r = idx >> 3, q = idx & 7;
            float4 v = *(const float4*)(E + (size_t)(row0 + r) * DD + k0 + q * 4);
            uint32_t off = (uint32_t)(r * 128 + q * 16);
            off ^= (off >> 3) & 0x70;
            *(float4*)(dsm + A_off[b] + off) = v;
        }
#pragma unroll
        for (int i = 0; i < 4; i++) {   // B: 256 rows x 32 f32
            int idx = tid + i * 512;
            int r = idx >> 3, q = idx & 7;
            float4 v = *(const float4*)(E + (size_t)(col0 + r) * DD + k0 + q * 4);
            uint32_t off = (uint32_t)(r * 128 + q * 16);
            off ^= (off >> 3) & 0x70;
            *(float4*)(dsm + B_off[b] + off) = v;
        }
        __syncthreads();
        if (tid == 0) {
            fence_async_smem();
            uint64_t a0 = make_desc(sb + A_off[b]);           // rows 0-127
            uint64_t a1 = make_desc(sb + A_off[b] + 16384);   // rows 128-255
            uint64_t bd = make_desc(sb + B_off[b]);
            uint32_t en = (c != 0);
#pragma unroll
            for (int ks = 0; ks < 4; ks++) {
                uint32_t e = en | (ks != 0);
                mma_tf32_ss(tmem,       a0 + ks * 2, bd + ks * 2, MMA_IDESC, e);
                mma_tf32_ss(tmem + 256, a1 + ks * 2, bd + ks * 2, MMA_IDESC, e);
            }
            mma_commit(sb + 16 + b * 8);
        }
    }
    mbar_wait(sb + 16, ph0);
    mbar_wait(sb + 24, ph1);
    tc_fence_after();

    // Epilogue: warp w -> subpartition s_=w&3, col group g_=w>>2 (64 cols)
    int s_ = wid & 3, g_ = wid >> 2;
#pragma unroll
    for (int h = 0; h < 2; h++) {
        int r_tile = h * 128 + s_ * 32 + lane;
        float xr = xR[r_tile];
        int   trg = tR[r_tile];
        float mp = 0.f, mn = INFINITY;   // d2 >= 0; 0 is identity for masked max
#pragma unroll
        for (int cb = 0; cb < 2; cb++) {
            uint32_t regs[32];
            LDTM_X32(regs, tmem + h * 256 + g_ * 64 + cb * 32);
            tc_wait_ld();
#pragma unroll
            for (int j = 0; j < 32; j++) {
                int cl = g_ * 64 + cb * 32 + j;
                float g  = __uint_as_float(regs[j]);
                float d2 = fmaxf(xr + xC[cl] - 2.f * g, 0.f);
                bool match = (trg == tC[cl]);
                if (match) mp = fmaxf(mp, d2);
                else       mn = fminf(mn, d2);
                if (offdiag) {
                    // per-column cross-lane reduce (rows of this warp)
                    float cp = match ? d2 : -1.f;       // int-negative, never wins
                    float cn = match ? INFINITY : d2;
#pragma unroll
                    for (int o = 16; o > 0; o >>= 1) {
                        cp = fmaxf(cp, __shfl_xor_sync(0xFFFFFFFF, cp, o));
                        cn = fminf(cn, __shfl_xor_sync(0xFFFFFFFF, cn, o));
                    }
                    if (lane == 0) {
                        atomicMax(&colap[cl], __float_as_int(cp));
                        atomicMin(&colan[cl], __float_as_int(cn));
                    }
                }
            }
        }
        atomicMax(&rowap[r_tile], __float_as_int(mp));
        atomicMin(&rowan[r_tile], __float_as_int(mn));
    }
    tc_fence_before();
    __syncthreads();

    if (tid < 256) {
        atomicMax((int*)&out[2 + row0 + tid],      rowap[tid]);
        atomicMin((int*)&out[2 + NN + row0 + tid], rowan[tid]);
        if (offdiag) {
            atomicMax((int*)&out[2 + col0 + tid],      colap[tid]);
            atomicMin((int*)&out[2 + NN + col0 + tid], colan[tid]);
        }
    }
    __syncthreads();
    if (wid == 0) tmem_dealloc(tmem, 512);

#else  // ---------- generic-arch fallback: FFMA SGEMM, two passes if offdiag ---
    float* As = (float*)(dsm);               // [16][264]
    float* Bs = (float*)(dsm + 16896);       // [16][264]
    float* xR = (float*)(dsm + 33792);
    float* xC = (float*)(dsm + 34816);
    int*   tR = (int*)(dsm + 35840);
    int*   tC = (int*)(dsm + 36864);
#define AS(k, r) As[(k) * 264 + (r)]
#define BS(k, r) Bs[(k) * 264 + (r)]

    int tx = tid & 15, ty = tid >> 4;
    int npass = offdiag ? 2 : 1;
    for (int p = 0; p < npass; p++) {
        int r0 = p ? col0 : row0;
        int c0base = p ? row0 : col0;
        if (tid < 256) {
            xR[tid] = g_xx[r0 + tid];
            tR[tid] = g_tgt[r0 + tid];
        } else {
            int j = tid - 256;
            xC[j] = g_xx[c0base + j];
            tC[j] = g_tgt[c0base + j];
        }
        __syncthreads();
        for (int hh = 0; hh < 2; hh++) {
            int c0 = c0base + hh * 128;
            float acc[8][8];
#pragma unroll
            for (int m = 0; m < 8; m++)
#pragma unroll
                for (int n = 0; n < 8; n++) acc[m][n] = 0.f;
            for (int k0 = 0; k0 < DD; k0 += 16) {
#pragma unroll
                for (int l = 0; l < 2; l++) {
                    int q = tid + l * 512;
                    int r = q >> 2, kq = (q & 3) << 2;
                    float4 v = *(const float4*)(E + (size_t)(r0 + r) * DD + k0 + kq);
                    AS(kq + 0, r) = v.x; AS(kq + 1, r) = v.y;
                    AS(kq + 2, r) = v.z; AS(kq + 3, r) = v.w;
                }
                if (tid < 512) {
                    int q = tid;
                    int r = q >> 2, kq = (q & 3) << 2;
                    float4 w = *(const float4*)(E + (size_t)(c0 + r) * DD + k0 + kq);
                    BS(kq + 0, r) = w.x; BS(kq + 1, r) = w.y;
                    BS(kq + 2, r) = w.z; BS(kq + 3, r) = w.w;
                }
                __syncthreads();
#pragma unroll
                for (int k = 0; k < 16; k++) {
                    float a[8], b[8];
#pragma unroll
                    for (int m = 0; m < 8; m++) a[m] = AS(k, ty + m * 32);
#pragma unroll
                    for (int n = 0; n < 8; n++) b[n] = BS(k, tx + n * 16);
#pragma unroll
                    for (int m = 0; m < 8; m++)
#pragma unroll
                        for (int n = 0; n < 8; n++)
                            acc[m][n] = fmaf(a[m], b[n], acc[m][n]);
                }
                __syncthreads();
            }
#pragma unroll
            for (int m = 0; m < 8; m++) {
                int   lr  = ty + m * 32;
                int   trg = tR[lr];
                float xr  = xR[lr];
                float mp = 0.f, mn = INFINITY;
#pragma unroll
                for (int n = 0; n < 8; n++) {
                    int   lc = hh * 128 + tx + n * 16;
                    float d2 = fmaxf(xr + xC[lc] - 2.f * acc[m][n], 0.f);
                    if (trg == tC[lc]) mp = fmaxf(mp, d2);
                    else               mn = fminf(mn, d2);
                }
#pragma unroll
                for (int o = 8; o > 0; o >>= 1) {
                    mp = fmaxf(mp, __shfl_xor_sync(0xFFFFFFFF, mp, o));
                    mn = fminf(mn, __shfl_xor_sync(0xFFFFFFFF, mn, o));
                }
                if (tx == 0) {
                    atomicMax((int*)&out[2 + r0 + lr],      __float_as_int(mp));
                    atomicMin((int*)&out[2 + NN + r0 + lr], __float_as_int(mn));
                }
            }
            __syncthreads();
        }
        __syncthreads();
    }
#undef AS
#undef BS
#endif
}

// ---------------- final deterministic reduce (+ d2 -> dist) ----------------
__global__ void k_finish(float* __restrict__ out) {
    int t = threadIdx.x;
    float str = 0.f, sce = 0.f;
    for (int i = t; i < NN; i += 256) {
        float ap = sqrtf(fmaxf(out[2 + i],      1e-12f));
        float an = sqrtf(fmaxf(out[2 + NN + i], 1e-12f));
        out[2 + i]      = ap;
        out[2 + NN + i] = an;
        str += fmaxf(ap - an + MARGIN_F, 0.f);
        sce += g_ce_row[i];
    }
    __shared__ float s1[256], s2[256];
    s1[t] = str; s2[t] = sce;
    __syncthreads();
    for (int o = 128; o > 0; o >>= 1) {
        if (t < o) { s1[t] += s1[t + o]; s2[t] += s2[t + o]; }
        __syncthreads();
    }
    if (t == 0) {
        out[0] = s2[0] / (float)NN;  // id_loss
        out[1] = s1[0] / (float)NN;  // tri_loss
    }
}

extern "C" void kernel_launch(void* const* d_in, const int* in_sizes, int n_in,
                              void* d_out, int out_size) {
    const float* E = (const float*)d_in[0];   // embeddings [4096, 2048]
    const float* P = (const float*)d_in[1];   // pred_ids   [4096, 8192]
    const int*   T = (const int*)d_in[2];     // target_ids [4096] int32
    float* out = (float*)d_out;               // [8194]

    // One-time infra (streams/events are not device memory; same work every call)
    static cudaStream_t s_side = 0;
    static cudaEvent_t  ev_fork = 0, ev_join = 0;
    if (!s_side) {
        cudaStreamCreateWithFlags(&s_side, cudaStreamNonBlocking);
        cudaEventCreateWithFlags(&ev_fork, cudaEventDisableTiming);
        cudaEventCreateWithFlags(&ev_join, cudaEventDisableTiming);
    }
    cudaFuncSetAttribute(k_dist, cudaFuncAttributeMaxDynamicSharedMemorySize,
                         DSMEM_BYTES);

    k_init<<<(NN + 255) / 256, 256>>>(T, out);

    // fork: k_ce runs concurrently with k_xx + k_dist
    cudaEventRecord(ev_fork, 0);
    cudaStreamWaitEvent(s_side, ev_fork, 0);
    k_ce<<<NN, 256, 0, s_side>>>(P);
    cudaEventRecord(ev_join, s_side);

    k_xx<<<NN, 256>>>(E);
    k_dist<<<136, 512, DSMEM_BYTES>>>(E, out);

    // join, then finish
    cudaStreamWaitEvent(0, ev_join, 0);
    k_finish<<<1, 256>>>(out);
}

// round 7
// speedup vs baseline: 14.2948x; 1.1175x over previous
#include <cuda_runtime.h>
#include <math.h>
#include <stdint.h>

#define NN 4096
#define DD 2048
#define CC 8192
#define MARGIN_F 0.3f
#define EPSLS 0.1f

#if defined(__CUDA_ARCH__) && (__CUDA_ARCH__ >= 1000) &&                        \
    (defined(__CUDA_ARCH_FEAT_SM103_ALL) || defined(__CUDA_ARCH_FEAT_SM100_ALL) || \
     defined(__CUDA_ARCH_SPECIFIC__) || defined(__CUDA_ARCH_FAMILY_SPECIFIC__))
#define TC_OK 1
#else
#define TC_OK 0
#endif

// ---------------- device scratch ----------------
__device__ float g_xx[NN];
__device__ float g_ce_row[NN];
__device__ int   g_tgt[NN];

// ---------------- PTX helpers ----------------
__device__ __forceinline__ uint32_t smem_u32(const void* p) {
    uint32_t a;
    asm("{ .reg .u64 t; cvta.to.shared.u64 t, %1; cvt.u32.u64 %0, t; }"
        : "=r"(a) : "l"(p));
    return a;
}
__device__ __forceinline__ void cp_async16(uint32_t dst, const void* src) {
    asm volatile("cp.async.cg.shared.global [%0], [%1], 16;"
                 :: "r"(dst), "l"(src) : "memory");
}
__device__ __forceinline__ void cp_commit() {
    asm volatile("cp.async.commit_group;" ::: "memory");
}
template <int N>
__device__ __forceinline__ void cp_wait() {
    asm volatile("cp.async.wait_group %0;" :: "n"(N) : "memory");
}

#if TC_OK
__device__ __forceinline__ void mbar_init(uint32_t a, uint32_t n) {
    asm volatile("mbarrier.init.shared.b64 [%0], %1;" :: "r"(a), "r"(n) : "memory");
}
__device__ __forceinline__ void mbar_wait(uint32_t a, uint32_t ph) {
    asm volatile(
        "{\n\t"
        ".reg .pred P;\n\t"
        "WL_%=:\n\t"
        "mbarrier.try_wait.parity.acquire.cta.shared::cta.b64 P, [%0], %1, 0x989680;\n\t"
        "@P bra WD_%=;\n\t"
        "bra WL_%=;\n\t"
        "WD_%=:\n\t"
        "}" :: "r"(a), "r"(ph) : "memory");
}
__device__ __forceinline__ void tmem_alloc(uint32_t smem_dst, uint32_t ncols) {
    asm volatile("tcgen05.alloc.cta_group::1.sync.aligned.shared::cta.b32 [%0], %1;"
                 :: "r"(smem_dst), "r"(ncols) : "memory");
}
__device__ __forceinline__ void tmem_dealloc(uint32_t tmem, uint32_t ncols) {
    asm volatile("tcgen05.dealloc.cta_group::1.sync.aligned.b32 %0, %1;"
                 :: "r"(tmem), "r"(ncols));
}
__device__ __forceinline__ void tmem_relinq() {
    asm volatile("tcgen05.relinquish_alloc_permit.cta_group::1.sync.aligned;");
}
__device__ __forceinline__ void mma_commit(uint32_t mbar) {
    asm volatile("tcgen05.commit.cta_group::1.mbarrier::arrive::one.shared::cluster.b64 [%0];"
                 :: "r"(mbar) : "memory");
}
__device__ __forceinline__ void fence_async_smem() {
    asm volatile("fence.proxy.async.shared::cta;" ::: "memory");
}
__device__ __forceinline__ void tc_fence_after() {
    asm volatile("tcgen05.fence::after_thread_sync;" ::: "memory");
}
__device__ __forceinline__ void tc_fence_before() {
    asm volatile("tcgen05.fence::before_thread_sync;" ::: "memory");
}
__device__ __forceinline__ void tc_wait_ld() {
    asm volatile("tcgen05.wait::ld.sync.aligned;" ::: "memory");
}
__device__ __forceinline__ void mma_tf32_ss(uint32_t d_tmem, uint64_t a_desc,
                                            uint64_t b_desc, uint32_t idesc,
                                            uint32_t en) {
    asm volatile(
        "{\n\t"
        ".reg .pred p;\n\t"
        "setp.ne.u32 p, %5, 0;\n\t"
        "tcgen05.mma.cta_group::1.kind::tf32 [%0], %1, %2, %3, {%4, %4, %4, %4}, p;\n\t"
        "}"
        :: "r"(d_tmem), "l"(a_desc), "l"(b_desc), "r"(idesc), "r"(0u), "r"(en)
        : "memory");
}
#define LDTM_X32(r, addr)                                                        \
    asm volatile(                                                                \
        "tcgen05.ld.sync.aligned.32x32b.x32.b32 "                                \
        "{%0, %1, %2, %3, %4, %5, %6, %7, "                                      \
        " %8, %9, %10, %11, %12, %13, %14, %15, "                                \
        " %16, %17, %18, %19, %20, %21, %22, %23, "                              \
        " %24, %25, %26, %27, %28, %29, %30, %31}, [%32];"                       \
        : "=r"((r)[0]),  "=r"((r)[1]),  "=r"((r)[2]),  "=r"((r)[3]),             \
          "=r"((r)[4]),  "=r"((r)[5]),  "=r"((r)[6]),  "=r"((r)[7]),             \
          "=r"((r)[8]),  "=r"((r)[9]),  "=r"((r)[10]), "=r"((r)[11]),            \
          "=r"((r)[12]), "=r"((r)[13]), "=r"((r)[14]), "=r"((r)[15]),            \
          "=r"((r)[16]), "=r"((r)[17]), "=r"((r)[18]), "=r"((r)[19]),            \
          "=r"((r)[20]), "=r"((r)[21]), "=r"((r)[22]), "=r"((r)[23]),            \
          "=r"((r)[24]), "=r"((r)[25]), "=r"((r)[26]), "=r"((r)[27]),            \
          "=r"((r)[28]), "=r"((r)[29]), "=r"((r)[30]), "=r"((r)[31])             \
        : "r"(addr))

// SW128 K-major smem descriptor: layout=2, version=1, SBO=64, LBO=1
__device__ __forceinline__ uint64_t make_desc(uint32_t smem_addr) {
    const uint64_t base = (uint64_t(2) << 61) | (uint64_t(1) << 46) |
                          (uint64_t(64) << 32) | (uint64_t(1) << 16);
    return base | ((uint64_t)(smem_addr >> 4) & 0x3FFF);
}
#define MMA_IDESC ((1u << 4) | (2u << 7) | (2u << 10) | (32u << 17) | (8u << 24))
#endif  // TC_OK

// ---------------- init ----------------
__global__ void k_init(const int* __restrict__ tgt, float* __restrict__ out) {
    int i = blockIdx.x * blockDim.x + threadIdx.x;
    if (i < NN) {
        int t = tgt[i];
        g_tgt[i] = min(max(t, 0), CC - 1);
        out[2 + i] = 0.0f;
        ((int*)out)[2 + NN + i] = 0x7F800000;
    }
}

// ---------------- per-row sum of squares ----------------
__global__ void k_xx(const float* __restrict__ E) {
    int r = blockIdx.x;
    const float4* row = (const float4*)(E + (size_t)r * DD);
    float s = 0.f;
    for (int i = threadIdx.x; i < DD / 4; i += 256) {
        float4 v = row[i];
        s += v.x * v.x + v.y * v.y + v.z * v.z + v.w * v.w;
    }
    __shared__ float sm[256];
    sm[threadIdx.x] = s;
    __syncthreads();
    for (int o = 128; o > 0; o >>= 1) {
        if (threadIdx.x < o) sm[threadIdx.x] += sm[threadIdx.x + o];
        __syncthreads();
    }
    if (threadIdx.x == 0) g_xx[r] = sm[0];
}

// ---------------- label-smoothed CE: register-resident, single pass ----------
__global__ void __launch_bounds__(256) k_ce(const float* __restrict__ logits) {
    int r = blockIdx.x;
    int t = threadIdx.x;
    int lane = t & 31, wrp = t >> 5;
    const float4* row = (const float4*)(logits + (size_t)r * CC);

    float4 v[8];
    float mx = -INFINITY, s = 0.f;
#pragma unroll
    for (int i = 0; i < 8; i++) {
        v[i] = row[t + i * 256];
        mx = fmaxf(mx, fmaxf(fmaxf(v[i].x, v[i].y), fmaxf(v[i].z, v[i].w)));
        s += v[i].x + v[i].y + v[i].z + v[i].w;
    }
    __shared__ float smx[8], ssm[8], sse[8];
#pragma unroll
    for (int o = 16; o > 0; o >>= 1) {
        mx = fmaxf(mx, __shfl_xor_sync(0xFFFFFFFF, mx, o));
        s += __shfl_xor_sync(0xFFFFFFFF, s, o);
    }
    if (lane == 0) { smx[wrp] = mx; ssm[wrp] = s; }
    __syncthreads();
    if (wrp == 0) {
        float m2 = (lane < 8) ? smx[lane] : -INFINITY;
        float s2 = (lane < 8) ? ssm[lane] : 0.f;
#pragma unroll
        for (int o = 4; o > 0; o >>= 1) {
            m2 = fmaxf(m2, __shfl_xor_sync(0xFFFFFFFF, m2, o));
            s2 += __shfl_xor_sync(0xFFFFFFFF, s2, o);
        }
        if (lane == 0) { smx[0] = m2; ssm[0] = s2; }
    }
    __syncthreads();
    mx = smx[0];
    s  = ssm[0];

    float se = 0.f;
#pragma unroll
    for (int i = 0; i < 8; i++) {
        se += __expf(v[i].x - mx) + __expf(v[i].y - mx) +
              __expf(v[i].z - mx) + __expf(v[i].w - mx);
    }
#pragma unroll
    for (int o = 16; o > 0; o >>= 1) se += __shfl_xor_sync(0xFFFFFFFF, se, o);
    if (lane == 0) sse[wrp] = se;
    __syncthreads();
    if (t == 0) {
        float tot = 0.f;
#pragma unroll
        for (int i = 0; i < 8; i++) tot += sse[i];
        float lse = mx + logf(tot);
        float lt  = logits[(size_t)r * CC + g_tgt[r]];
        g_ce_row[r] = lse - (1.f - EPSLS) * lt - EPSLS * (s / (float)CC);
    }
}

// ---------------- symmetric Gram + batch-hard mining (on d2) ----------------
// Upper-triangular tiling: 136 CTAs, tile (bi,bj) bi<=bj, 256x256 each.
// cp.async 3-stage pipeline (A+B = 64KB/stage), tf32 tcgen05 into 512-col TMEM.
#define NSTAGE 3
#define STG_BASE 16384
#define STG_SZ   65536
#define DSMEM_BYTES (STG_BASE + NSTAGE * STG_SZ + 1024)

__global__ void __launch_bounds__(512, 1) k_dist(const float* __restrict__ E,
                                                 float* __restrict__ out) {
    extern __shared__ char dsm_raw[];
    char* dsm = (char*)(((uintptr_t)dsm_raw + 1023) & ~(uintptr_t)1023);
    int tid = threadIdx.x;

    // triangle mapping: bid -> (bi, bj), bi<=bj over 16x16 tiles
    int bi = 0, rem = blockIdx.x;
#pragma unroll 1
    while (rem >= 16 - bi) { rem -= 16 - bi; bi++; }
    int bj = bi + rem;
    int row0 = bi * 256, col0 = bj * 256;
    bool offdiag = (bi != bj);

#if TC_OK
    uint32_t sb = smem_u32(dsm);
    float* xR = (float*)(dsm + 64);
    float* xC = (float*)(dsm + 1088);
    int*   tR = (int*)(dsm + 2112);
    int*   tC = (int*)(dsm + 3136);
    int* rowap = (int*)(dsm + 4160);
    int* rowan = (int*)(dsm + 5184);
    int* colap = (int*)(dsm + 6208);
    int* colan = (int*)(dsm + 7232);
    int wid = tid >> 5, lane = tid & 31;

    if (wid == 0) {
        tmem_alloc(sb + 0, 512);
        tmem_relinq();
    }
    if (tid == 0) {
        mbar_init(sb + 16, 1);
        mbar_init(sb + 24, 1);
        mbar_init(sb + 32, 1);
    }
    if (tid < 256) {
        xR[tid] = g_xx[row0 + tid];
        tR[tid] = g_tgt[row0 + tid];
        rowap[tid] = 0;
        colap[tid] = 0;
    } else {
        int j = tid - 256;
        xC[j] = g_xx[col0 + j];
        tC[j] = g_tgt[col0 + j];
        rowan[j] = 0x7F800000;
        colan[j] = 0x7F800000;
    }
    __syncthreads();
    uint32_t tmem;
    asm volatile("ld.shared.b32 %0, [%1];" : "=r"(tmem) : "r"(sb + 0));

    // per-thread addressing for the chunk loader: 4 A + 4 B float4 per thread
    int lr_ = tid >> 3;            // row within tile (0..255 over 4 iters: +64/iter? no)
    // Each iter i handles 512 float4: idx = tid + i*512; r = idx>>3 in [0,256)
    // thread's swizzled smem offset per iter precomputed below in the loop.

    // loader lambda (macro-style)
#define LOAD_CHUNK(c_, s_)                                                       \
    do {                                                                         \
        int k0_ = (c_) * 32;                                                     \
        uint32_t A_s = sb + STG_BASE + (s_) * STG_SZ;                            \
        uint32_t B_s = A_s + 32768u;                                             \
        _Pragma("unroll")                                                        \
        for (int i_ = 0; i_ < 4; i_++) {                                         \
            int idx_ = tid + i_ * 512;                                           \
            int r_ = idx_ >> 3, q_ = idx_ & 7;                                   \
            uint32_t off_ = (uint32_t)(r_ * 128 + q_ * 16);                      \
            off_ ^= (off_ >> 3) & 0x70;                                          \
            cp_async16(A_s + off_, E + (size_t)(row0 + r_) * DD + k0_ + q_ * 4); \
        }                                                                        \
        _Pragma("unroll")                                                        \
        for (int i_ = 0; i_ < 4; i_++) {                                         \
            int idx_ = tid + i_ * 512;                                           \
            int r_ = idx_ >> 3, q_ = idx_ & 7;                                   \
            uint32_t off_ = (uint32_t)(r_ * 128 + q_ * 16);                      \
            off_ ^= (off_ >> 3) & 0x70;                                          \
            cp_async16(B_s + off_, E + (size_t)(col0 + r_) * DD + k0_ + q_ * 4); \
        }                                                                        \
        cp_commit();                                                             \
    } while (0)

    // prologue: chunks 0 and 1 in flight
    LOAD_CHUNK(0, 0);
    LOAD_CHUNK(1, 1);

    uint32_t phase[NSTAGE] = {0, 0, 0};
    const int NC = DD / 32;  // 64
    for (int c = 0; c < NC; c++) {
        int s = c % NSTAGE;
        int pf = c + 2;
        if (pf < NC) {
            int sp = pf % NSTAGE;
            if (pf >= NSTAGE) {
                mbar_wait(sb + 16 + sp * 8, phase[sp]);
                phase[sp] ^= 1;
            }
            LOAD_CHUNK(pf, sp);
        } else {
            cp_commit();  // empty group keeps wait_group accounting aligned
        }
        cp_wait<2>();     // chunk c fully in smem
        __syncthreads();
        if (tid == 0) {
            fence_async_smem();
            uint32_t A_s = sb + STG_BASE + s * STG_SZ;
            uint64_t a0 = make_desc(A_s);
            uint64_t a1 = make_desc(A_s + 16384);
            uint64_t bd = make_desc(A_s + 32768);
            uint32_t en = (c != 0);
#pragma unroll
            for (int ks = 0; ks < 4; ks++) {
                uint32_t e = en | (ks != 0);
                mma_tf32_ss(tmem,       a0 + ks * 2, bd + ks * 2, MMA_IDESC, e);
                mma_tf32_ss(tmem + 256, a1 + ks * 2, bd + ks * 2, MMA_IDESC, e);
            }
            mma_commit(sb + 16 + s * 8);
        }
    }
    // drain the last commit on each stage
#pragma unroll
    for (int s = 0; s < NSTAGE; s++) mbar_wait(sb + 16 + s * 8, phase[s]);
    tc_fence_after();

    // Epilogue: warp w -> subpartition s_=w&3, col group g_=w>>2 (64 cols)
    int s_ = wid & 3, g_ = wid >> 2;
#pragma unroll
    for (int h = 0; h < 2; h++) {
        int r_tile = h * 128 + s_ * 32 + lane;
        float xr = xR[r_tile];
        int   trg = tR[r_tile];
        float mp = 0.f, mn = INFINITY;
#pragma unroll
        for (int cb = 0; cb < 2; cb++) {
            uint32_t regs[32];
            LDTM_X32(regs, tmem + h * 256 + g_ * 64 + cb * 32);
            tc_wait_ld();
#pragma unroll
            for (int j = 0; j < 32; j++) {
                int cl = g_ * 64 + cb * 32 + j;
                float g  = __uint_as_float(regs[j]);
                float d2 = fmaxf(xr + xC[cl] - 2.f * g, 0.f);
                bool match = (trg == tC[cl]);
                if (match) mp = fmaxf(mp, d2);
                else       mn = fminf(mn, d2);
                if (offdiag) {
                    float cp = match ? d2 : -1.f;
                    float cn = match ? INFINITY : d2;
#pragma unroll
                    for (int o = 16; o > 0; o >>= 1) {
                        cp = fmaxf(cp, __shfl_xor_sync(0xFFFFFFFF, cp, o));
                        cn = fminf(cn, __shfl_xor_sync(0xFFFFFFFF, cn, o));
                    }
                    if (lane == 0) {
                        atomicMax(&colap[cl], __float_as_int(cp));
                        atomicMin(&colan[cl], __float_as_int(cn));
                    }
                }
            }
        }
        atomicMax(&rowap[r_tile], __float_as_int(mp));
        atomicMin(&rowan[r_tile], __float_as_int(mn));
    }
    tc_fence_before();
    __syncthreads();

    if (tid < 256) {
        atomicMax((int*)&out[2 + row0 + tid],      rowap[tid]);
        atomicMin((int*)&out[2 + NN + row0 + tid], rowan[tid]);
        if (offdiag) {
            atomicMax((int*)&out[2 + col0 + tid],      colap[tid]);
            atomicMin((int*)&out[2 + NN + col0 + tid], colan[tid]);
        }
    }
    __syncthreads();
    if (wid == 0) tmem_dealloc(tmem, 512);
#undef LOAD_CHUNK

#else  // ---------- generic-arch fallback: FFMA SGEMM, two passes if offdiag ---
    float* As = (float*)(dsm);
    float* Bs = (float*)(dsm + 16896);
    float* xR = (float*)(dsm + 33792);
    float* xC = (float*)(dsm + 34816);
    int*   tR = (int*)(dsm + 35840);
    int*   tC = (int*)(dsm + 36864);
#define AS(k, r) As[(k) * 264 + (r)]
#define BS(k, r) Bs[(k) * 264 + (r)]

    int tx = tid & 15, ty = tid >> 4;
    int npass = offdiag ? 2 : 1;
    for (int p = 0; p < npass; p++) {
        int r0 = p ? col0 : row0;
        int c0base = p ? row0 : col0;
        if (tid < 256) {
            xR[tid] = g_xx[r0 + tid];
            tR[tid] = g_tgt[r0 + tid];
        } else {
            int j = tid - 256;
            xC[j] = g_xx[c0base + j];
            tC[j] = g_tgt[c0base + j];
        }
        __syncthreads();
        for (int hh = 0; hh < 2; hh++) {
            int c0 = c0base + hh * 128;
            float acc[8][8];
#pragma unroll
            for (int m = 0; m < 8; m++)
#pragma unroll
                for (int n = 0; n < 8; n++) acc[m][n] = 0.f;
            for (int k0 = 0; k0 < DD; k0 += 16) {
#pragma unroll
                for (int l = 0; l < 2; l++) {
                    int q = tid + l * 512;
                    int r = q >> 2, kq = (q & 3) << 2;
                    float4 v = *(const float4*)(E + (size_t)(r0 + r) * DD + k0 + kq);
                    AS(kq + 0, r) = v.x; AS(kq + 1, r) = v.y;
                    AS(kq + 2, r) = v.z; AS(kq + 3, r) = v.w;
                }
                if (tid < 512) {
                    int q = tid;
                    int r = q >> 2, kq = (q & 3) << 2;
                    float4 w = *(const float4*)(E + (size_t)(c0 + r) * DD + k0 + kq);
                    BS(kq + 0, r) = w.x; BS(kq + 1, r) = w.y;
                    BS(kq + 2, r) = w.z; BS(kq + 3, r) = w.w;
                }
                __syncthreads();
#pragma unroll
                for (int k = 0; k < 16; k++) {
                    float a[8], b[8];
#pragma unroll
                    for (int m = 0; m < 8; m++) a[m] = AS(k, ty + m * 32);
#pragma unroll
                    for (int n = 0; n < 8; n++) b[n] = BS(k, tx + n * 16);
#pragma unroll
                    for (int m = 0; m < 8; m++)
#pragma unroll
                        for (int n = 0; n < 8; n++)
                            acc[m][n] = fmaf(a[m], b[n], acc[m][n]);
                }
                __syncthreads();
            }
#pragma unroll
            for (int m = 0; m < 8; m++) {
                int   lr  = ty + m * 32;
                int   trg = tR[lr];
                float xr  = xR[lr];
                float mp = 0.f, mn = INFINITY;
#pragma unroll
                for (int n = 0; n < 8; n++) {
                    int   lc = hh * 128 + tx + n * 16;
                    float d2 = fmaxf(xr + xC[lc] - 2.f * acc[m][n], 0.f);
                    if (trg == tC[lc]) mp = fmaxf(mp, d2);
                    else               mn = fminf(mn, d2);
                }
#pragma unroll
                for (int o = 8; o > 0; o >>= 1) {
                    mp = fmaxf(mp, __shfl_xor_sync(0xFFFFFFFF, mp, o));
                    mn = fminf(mn, __shfl_xor_sync(0xFFFFFFFF, mn, o));
                }
                if (tx == 0) {
                    atomicMax((int*)&out[2 + r0 + lr],      __float_as_int(mp));
                    atomicMin((int*)&out[2 + NN + r0 + lr], __float_as_int(mn));
                }
            }
            __syncthreads();
        }
        __syncthreads();
    }
#undef AS
#undef BS
#endif
}

// ---------------- final deterministic reduce (+ d2 -> dist) ----------------
__global__ void k_finish(float* __restrict__ out) {
    int t = threadIdx.x;
    float str = 0.f, sce = 0.f;
    for (int i = t; i < NN; i += 256) {
        float ap = sqrtf(fmaxf(out[2 + i],      1e-12f));
        float an = sqrtf(fmaxf(out[2 + NN + i], 1e-12f));
        out[2 + i]      = ap;
        out[2 + NN + i] = an;
        str += fmaxf(ap - an + MARGIN_F, 0.f);
        sce += g_ce_row[i];
    }
    __shared__ float s1[256], s2[256];
    s1[t] = str; s2[t] = sce;
    __syncthreads();
    for (int o = 128; o > 0; o >>= 1) {
        if (t < o) { s1[t] += s1[t + o]; s2[t] += s2[t + o]; }
        __syncthreads();
    }
    if (t == 0) {
        out[0] = s2[0] / (float)NN;  // id_loss
        out[1] = s1[0] / (float)NN;  // tri_loss
    }
}

extern "C" void kernel_launch(void* const* d_in, const int* in_sizes, int n_in,
                              void* d_out, int out_size) {
    const float* E = (const float*)d_in[0];
    const float* P = (const float*)d_in[1];
    const int*   T = (const int*)d_in[2];
    float* out = (float*)d_out;

    static cudaStream_t s_side = 0;
    static cudaEvent_t  ev_fork = 0, ev_join = 0;
    if (!s_side) {
        cudaStreamCreateWithFlags(&s_side, cudaStreamNonBlocking);
        cudaEventCreateWithFlags(&ev_fork, cudaEventDisableTiming);
        cudaEventCreateWithFlags(&ev_join, cudaEventDisableTiming);
    }
    cudaFuncSetAttribute(k_dist, cudaFuncAttributeMaxDynamicSharedMemorySize,
                         DSMEM_BYTES);

    k_init<<<(NN + 255) / 256, 256>>>(T, out);

    cudaEventRecord(ev_fork, 0);
    cudaStreamWaitEvent(s_side, ev_fork, 0);
    k_ce<<<NN, 256, 0, s_side>>>(P);
    cudaEventRecord(ev_join, s_side);

    k_xx<<<NN, 256>>>(E);
    k_dist<<<136, 512, DSMEM_BYTES>>>(E, out);

    cudaStreamWaitEvent(0, ev_join, 0);
    k_finish<<<1, 256>>>(out);
}

// round 9
// speedup vs baseline: 17.4167x; 1.2184x over previous
#include <cuda_runtime.h>
#include <math.h>
#include <stdint.h>

#define NN 4096
#define DD 2048
#define CC 8192
#define MARGIN_F 0.3f
#define EPSLS 0.1f

#if defined(__CUDA_ARCH__) && (__CUDA_ARCH__ >= 1000) &&                        \
    (defined(__CUDA_ARCH_FEAT_SM103_ALL) || defined(__CUDA_ARCH_FEAT_SM100_ALL) || \
     defined(__CUDA_ARCH_SPECIFIC__) || defined(__CUDA_ARCH_FAMILY_SPECIFIC__))
#define TC_OK 1
#else
#define TC_OK 0
#endif

// ---------------- device scratch ----------------
__device__ float g_xx[NN];
__device__ float g_ce_row[NN];
__device__ int   g_tgt[NN];

// ---------------- PTX helpers ----------------
__device__ __forceinline__ uint32_t smem_u32(const void* p) {
    uint32_t a;
    asm("{ .reg .u64 t; cvta.to.shared.u64 t, %1; cvt.u32.u64 %0, t; }"
        : "=r"(a) : "l"(p));
    return a;
}
__device__ __forceinline__ void cp_async16(uint32_t dst, const void* src) {
    asm volatile("cp.async.cg.shared.global [%0], [%1], 16;"
                 :: "r"(dst), "l"(src) : "memory");
}

#if TC_OK
// .noinc is load-bearing: without it the arrive is increment-then-arrive
// (net zero) and a count-N barrier never completes.
__device__ __forceinline__ void cp_mbar_arrive_noinc(uint32_t mbar) {
    asm volatile("cp.async.mbarrier.arrive.noinc.shared::cta.b64 [%0];"
                 :: "r"(mbar) : "memory");
}
__device__ __forceinline__ void mbar_init(uint32_t a, uint32_t n) {
    asm volatile("mbarrier.init.shared.b64 [%0], %1;" :: "r"(a), "r"(n) : "memory");
}
__device__ __forceinline__ void mbar_wait(uint32_t a, uint32_t ph) {
    asm volatile(
        "{\n\t"
        ".reg .pred P;\n\t"
        "WL_%=:\n\t"
        "mbarrier.try_wait.parity.acquire.cta.shared::cta.b64 P, [%0], %1, 0x989680;\n\t"
        "@P bra WD_%=;\n\t"
        "bra WL_%=;\n\t"
        "WD_%=:\n\t"
        "}" :: "r"(a), "r"(ph) : "memory");
}
__device__ __forceinline__ void tmem_alloc(uint32_t smem_dst, uint32_t ncols) {
    asm volatile("tcgen05.alloc.cta_group::1.sync.aligned.shared::cta.b32 [%0], %1;"
                 :: "r"(smem_dst), "r"(ncols) : "memory");
}
__device__ __forceinline__ void tmem_dealloc(uint32_t tmem, uint32_t ncols) {
    asm volatile("tcgen05.dealloc.cta_group::1.sync.aligned.b32 %0, %1;"
                 :: "r"(tmem), "r"(ncols));
}
__device__ __forceinline__ void tmem_relinq() {
    asm volatile("tcgen05.relinquish_alloc_permit.cta_group::1.sync.aligned;");
}
__device__ __forceinline__ void mma_commit(uint32_t mbar) {
    asm volatile("tcgen05.commit.cta_group::1.mbarrier::arrive::one.shared::cluster.b64 [%0];"
                 :: "r"(mbar) : "memory");
}
__device__ __forceinline__ void fence_async_smem() {
    asm volatile("fence.proxy.async.shared::cta;" ::: "memory");
}
__device__ __forceinline__ void tc_fence_after() {
    asm volatile("tcgen05.fence::after_thread_sync;" ::: "memory");
}
__device__ __forceinline__ void tc_fence_before() {
    asm volatile("tcgen05.fence::before_thread_sync;" ::: "memory");
}
__device__ __forceinline__ void tc_wait_ld() {
    asm volatile("tcgen05.wait::ld.sync.aligned;" ::: "memory");
}
__device__ __forceinline__ void mma_tf32_ss(uint32_t d_tmem, uint64_t a_desc,
                                            uint64_t b_desc, uint32_t idesc,
                                            uint32_t en) {
    asm volatile(
        "{\n\t"
        ".reg .pred p;\n\t"
        "setp.ne.u32 p, %5, 0;\n\t"
        "tcgen05.mma.cta_group::1.kind::tf32 [%0], %1, %2, %3, {%4, %4, %4, %4}, p;\n\t"
        "}"
        :: "r"(d_tmem), "l"(a_desc), "l"(b_desc), "r"(idesc), "r"(0u), "r"(en)
        : "memory");
}
#define LDTM_X32(r, addr)                                                        \
    asm volatile(                                                                \
        "tcgen05.ld.sync.aligned.32x32b.x32.b32 "                                \
        "{%0, %1, %2, %3, %4, %5, %6, %7, "                                      \
        " %8, %9, %10, %11, %12, %13, %14, %15, "                                \
        " %16, %17, %18, %19, %20, %21, %22, %23, "                              \
        " %24, %25, %26, %27, %28, %29, %30, %31}, [%32];"                       \
        : "=r"((r)[0]),  "=r"((r)[1]),  "=r"((r)[2]),  "=r"((r)[3]),             \
          "=r"((r)[4]),  "=r"((r)[5]),  "=r"((r)[6]),  "=r"((r)[7]),             \
          "=r"((r)[8]),  "=r"((r)[9]),  "=r"((r)[10]), "=r"((r)[11]),            \
          "=r"((r)[12]), "=r"((r)[13]), "=r"((r)[14]), "=r"((r)[15]),            \
          "=r"((r)[16]), "=r"((r)[17]), "=r"((r)[18]), "=r"((r)[19]),            \
          "=r"((r)[20]), "=r"((r)[21]), "=r"((r)[22]), "=r"((r)[23]),            \
          "=r"((r)[24]), "=r"((r)[25]), "=r"((r)[26]), "=r"((r)[27]),            \
          "=r"((r)[28]), "=r"((r)[29]), "=r"((r)[30]), "=r"((r)[31])             \
        : "r"(addr))

// SW128 K-major smem descriptor
__device__ __forceinline__ uint64_t make_desc(uint32_t smem_addr) {
    const uint64_t base = (uint64_t(2) << 61) | (uint64_t(1) << 46) |
                          (uint64_t(64) << 32) | (uint64_t(1) << 16);
    return base | ((uint64_t)(smem_addr >> 4) & 0x3FFF);
}
#define MMA_IDESC ((1u << 4) | (2u << 7) | (2u << 10) | (32u << 17) | (8u << 24))
#endif  // TC_OK

// ---------------- init ----------------
__global__ void k_init(const int* __restrict__ tgt, float* __restrict__ out) {
    int i = blockIdx.x * blockDim.x + threadIdx.x;
    if (i < NN) {
        int t = tgt[i];
        g_tgt[i] = min(max(t, 0), CC - 1);
        out[2 + i] = 0.0f;
        ((int*)out)[2 + NN + i] = 0x7F800000;
    }
}

// ---------------- per-row sum of squares ----------------
__global__ void k_xx(const float* __restrict__ E) {
    int r = blockIdx.x;
    const float4* row = (const float4*)(E + (size_t)r * DD);
    float s = 0.f;
    for (int i = threadIdx.x; i < DD / 4; i += 256) {
        float4 v = row[i];
        s += v.x * v.x + v.y * v.y + v.z * v.z + v.w * v.w;
    }
    __shared__ float sm[256];
    sm[threadIdx.x] = s;
    __syncthreads();
    for (int o = 128; o > 0; o >>= 1) {
        if (threadIdx.x < o) sm[threadIdx.x] += sm[threadIdx.x + o];
        __syncthreads();
    }
    if (threadIdx.x == 0) g_xx[r] = sm[0];
}

// ---------------- label-smoothed CE: register-resident, single pass ----------
__global__ void __launch_bounds__(256) k_ce(const float* __restrict__ logits) {
    int r = blockIdx.x;
    int t = threadIdx.x;
    int lane = t & 31, wrp = t >> 5;
    const float4* row = (const float4*)(logits + (size_t)r * CC);

    float4 v[8];
    float mx = -INFINITY, s = 0.f;
#pragma unroll
    for (int i = 0; i < 8; i++) {
        v[i] = row[t + i * 256];
        mx = fmaxf(mx, fmaxf(fmaxf(v[i].x, v[i].y), fmaxf(v[i].z, v[i].w)));
        s += v[i].x + v[i].y + v[i].z + v[i].w;
    }
    __shared__ float smx[8], ssm[8], sse[8];
#pragma unroll
    for (int o = 16; o > 0; o >>= 1) {
        mx = fmaxf(mx, __shfl_xor_sync(0xFFFFFFFF, mx, o));
        s += __shfl_xor_sync(0xFFFFFFFF, s, o);
    }
    if (lane == 0) { smx[wrp] = mx; ssm[wrp] = s; }
    __syncthreads();
    if (wrp == 0) {
        float m2 = (lane < 8) ? smx[lane] : -INFINITY;
        float s2 = (lane < 8) ? ssm[lane] : 0.f;
#pragma unroll
        for (int o = 4; o > 0; o >>= 1) {
            m2 = fmaxf(m2, __shfl_xor_sync(0xFFFFFFFF, m2, o));
            s2 += __shfl_xor_sync(0xFFFFFFFF, s2, o);
        }
        if (lane == 0) { smx[0] = m2; ssm[0] = s2; }
    }
    __syncthreads();
    mx = smx[0];
    s  = ssm[0];

    float se = 0.f;
#pragma unroll
    for (int i = 0; i < 8; i++) {
        se += __expf(v[i].x - mx) + __expf(v[i].y - mx) +
              __expf(v[i].z - mx) + __expf(v[i].w - mx);
    }
#pragma unroll
    for (int o = 16; o > 0; o >>= 1) se += __shfl_xor_sync(0xFFFFFFFF, se, o);
    if (lane == 0) sse[wrp] = se;
    __syncthreads();
    if (t == 0) {
        float tot = 0.f;
#pragma unroll
        for (int i = 0; i < 8; i++) tot += sse[i];
        float lse = mx + logf(tot);
        float lt  = logits[(size_t)r * CC + g_tgt[r]];
        g_ce_row[r] = lse - (1.f - EPSLS) * lt - EPSLS * (s / (float)CC);
    }
}

// ---------------- symmetric Gram + batch-hard mining, warp-specialized -------
// 136 upper-tri tiles (bi<=bj), 256x256 per CTA. Warps 0-7 = producers
// (cp.async, full[s] via cp.async.mbarrier.arrive.noinc, count=256), warp 8 =
// MMA issuer (full-wait -> fence -> 8 MMAs -> commit empty[s]).
#define NSTAGE 3
#define STG_BASE 16384
#define STG_SZ   65536
#define DSMEM_BYTES (STG_BASE + NSTAGE * STG_SZ + 1024)

__global__ void __launch_bounds__(512, 1) k_dist(const float* __restrict__ E,
                                                 float* __restrict__ out) {
    extern __shared__ char dsm_raw[];
    char* dsm = (char*)(((uintptr_t)dsm_raw + 1023) & ~(uintptr_t)1023);
    int tid = threadIdx.x;

    int bi = 0, rem = blockIdx.x;
#pragma unroll 1
    while (rem >= 16 - bi) { rem -= 16 - bi; bi++; }
    int bj = bi + rem;
    int row0 = bi * 256, col0 = bj * 256;
    bool offdiag = (bi != bj);

#if TC_OK
    uint32_t sb = smem_u32(dsm);
    // smem map: 0 tmem ptr | 16,24,32 full[0..2] | 40,48,56 empty[0..2] | 64 done
    float* xR = (float*)(dsm + 128);
    float* xC = (float*)(dsm + 1152);
    int*   tR = (int*)(dsm + 2176);
    int*   tC = (int*)(dsm + 3200);
    int* rowap = (int*)(dsm + 4224);
    int* rowan = (int*)(dsm + 5248);
    int* colap = (int*)(dsm + 6272);
    int* colan = (int*)(dsm + 7296);
    int wid = tid >> 5, lane = tid & 31;

    if (wid == 0) {
        tmem_alloc(sb + 0, 512);
        tmem_relinq();
    }
    if (tid == 0) {
#pragma unroll
        for (int s = 0; s < NSTAGE; s++) {
            mbar_init(sb + 16 + s * 8, 256);  // full: one noinc-arrive per producer thread
            mbar_init(sb + 40 + s * 8, 1);    // empty: tcgen05 commit
        }
        mbar_init(sb + 64, 1);                // done
    }
    if (tid < 256) {
        xR[tid] = g_xx[row0 + tid];
        tR[tid] = g_tgt[row0 + tid];
        rowap[tid] = 0;
        colap[tid] = 0;
    } else {
        int j = tid - 256;
        xC[j] = g_xx[col0 + j];
        tC[j] = g_tgt[col0 + j];
        rowan[j] = 0x7F800000;
        colan[j] = 0x7F800000;
    }
    __syncthreads();
    uint32_t tmem;
    asm volatile("ld.shared.b32 %0, [%1];" : "=r"(tmem) : "r"(sb + 0));

    const int NC = DD / 32;  // 64 chunks

    if (wid < 8) {
        // ---------------- producers: 8 A + 8 B float4 per thread per chunk ----
        uint32_t offs[8];
        int rows[8], qs[8];
#pragma unroll
        for (int i = 0; i < 8; i++) {
            int idx = tid + i * 256;
            int r = idx >> 3, q = idx & 7;
            uint32_t off = (uint32_t)(r * 128 + q * 16);
            off ^= (off >> 3) & 0x70;
            offs[i] = off;
            rows[i] = r;
            qs[i] = q * 4;
        }
        const float* EA = E + (size_t)row0 * DD;
        const float* EB = E + (size_t)col0 * DD;
        uint32_t eph[NSTAGE] = {0, 0, 0};
#pragma unroll 1
        for (int c = 0; c < NC; c++) {
            int s = c % NSTAGE;
            if (c >= NSTAGE) {
                mbar_wait(sb + 40 + s * 8, eph[s]);
                eph[s] ^= 1;
            }
            uint32_t A_s = sb + STG_BASE + s * STG_SZ;
            uint32_t B_s = A_s + 32768u;
            int k0 = c * 32;
#pragma unroll
            for (int i = 0; i < 8; i++)
                cp_async16(A_s + offs[i], EA + (size_t)rows[i] * DD + k0 + qs[i]);
#pragma unroll
            for (int i = 0; i < 8; i++)
                cp_async16(B_s + offs[i], EB + (size_t)rows[i] * DD + k0 + qs[i]);
            cp_mbar_arrive_noinc(sb + 16 + s * 8);
        }
    } else if (wid == 8 && lane == 0) {
        // ---------------- MMA issuer ----------------
        uint32_t fph[NSTAGE] = {0, 0, 0};
#pragma unroll 1
        for (int c = 0; c < NC; c++) {
            int s = c % NSTAGE;
            mbar_wait(sb + 16 + s * 8, fph[s]);
            fph[s] ^= 1;
            fence_async_smem();
            uint32_t A_s = sb + STG_BASE + s * STG_SZ;
            uint64_t a0 = make_desc(A_s);
            uint64_t a1 = make_desc(A_s + 16384);
            uint64_t bd = make_desc(A_s + 32768);
            uint32_t en = (c != 0);
#pragma unroll
            for (int ks = 0; ks < 4; ks++) {
                uint32_t e = en | (ks != 0);
                mma_tf32_ss(tmem,       a0 + ks * 2, bd + ks * 2, MMA_IDESC, e);
                mma_tf32_ss(tmem + 256, a1 + ks * 2, bd + ks * 2, MMA_IDESC, e);
            }
            mma_commit(sb + 40 + s * 8);
        }
        mma_commit(sb + 64);  // fires when ALL prior MMAs complete
    }

    __syncthreads();
    mbar_wait(sb + 64, 0);
    tc_fence_after();

    // Epilogue: warp w -> subpartition s_=w&3, col group g_=w>>2 (64 cols)
    int s_ = wid & 3, g_ = wid >> 2;
#pragma unroll
    for (int h = 0; h < 2; h++) {
        int r_tile = h * 128 + s_ * 32 + lane;
        float xr = xR[r_tile];
        int   trg = tR[r_tile];
        float mp = 0.f, mn = INFINITY;
#pragma unroll
        for (int cb = 0; cb < 2; cb++) {
            uint32_t regs[32];
            LDTM_X32(regs, tmem + h * 256 + g_ * 64 + cb * 32);
            tc_wait_ld();
#pragma unroll
            for (int j = 0; j < 32; j++) {
                int cl = g_ * 64 + cb * 32 + j;
                float g  = __uint_as_float(regs[j]);
                float d2 = fmaxf(xr + xC[cl] - 2.f * g, 0.f);
                bool match = (trg == tC[cl]);
                if (match) mp = fmaxf(mp, d2);
                else       mn = fminf(mn, d2);
                if (offdiag) {
                    float cp = match ? d2 : -1.f;
                    float cn = match ? INFINITY : d2;
#pragma unroll
                    for (int o = 16; o > 0; o >>= 1) {
                        cp = fmaxf(cp, __shfl_xor_sync(0xFFFFFFFF, cp, o));
                        cn = fminf(cn, __shfl_xor_sync(0xFFFFFFFF, cn, o));
                    }
                    if (lane == 0) {
                        atomicMax(&colap[cl], __float_as_int(cp));
                        atomicMin(&colan[cl], __float_as_int(cn));
                    }
                }
            }
        }
        atomicMax(&rowap[r_tile], __float_as_int(mp));
        atomicMin(&rowan[r_tile], __float_as_int(mn));
    }
    tc_fence_before();
    __syncthreads();

    if (tid < 256) {
        atomicMax((int*)&out[2 + row0 + tid],      rowap[tid]);
        atomicMin((int*)&out[2 + NN + row0 + tid], rowan[tid]);
        if (offdiag) {
            atomicMax((int*)&out[2 + col0 + tid],      colap[tid]);
            atomicMin((int*)&out[2 + NN + col0 + tid], colan[tid]);
        }
    }
    __syncthreads();
    if (wid == 0) tmem_dealloc(tmem, 512);

#else  // ---------- generic-arch fallback: FFMA SGEMM, two passes if offdiag ---
    float* As = (float*)(dsm);
    float* Bs = (float*)(dsm + 16896);
    float* xR = (float*)(dsm + 33792);
    float* xC = (float*)(dsm + 34816);
    int*   tR = (int*)(dsm + 35840);
    int*   tC = (int*)(dsm + 36864);
#define AS(k, r) As[(k) * 264 + (r)]
#define BS(k, r) Bs[(k) * 264 + (r)]

    int tx = tid & 15, ty = tid >> 4;
    int npass = offdiag ? 2 : 1;
    for (int p = 0; p < npass; p++) {
        int r0 = p ? col0 : row0;
        int c0base = p ? row0 : col0;
        if (tid < 256) {
            xR[tid] = g_xx[r0 + tid];
            tR[tid] = g_tgt[r0 + tid];
        } else {
            int j = tid - 256;
            xC[j] = g_xx[c0base + j];
            tC[j] = g_tgt[c0base + j];
        }
        __syncthreads();
        for (int hh = 0; hh < 2; hh++) {
            int c0 = c0base + hh * 128;
            float acc[8][8];
#pragma unroll
            for (int m = 0; m < 8; m++)
#pragma unroll
                for (int n = 0; n < 8; n++) acc[m][n] = 0.f;
            for (int k0 = 0; k0 < DD; k0 += 16) {
#pragma unroll
                for (int l = 0; l < 2; l++) {
                    int q = tid + l * 512;
                    int r = q >> 2, kq = (q & 3) << 2;
                    float4 v = *(const float4*)(E + (size_t)(r0 + r) * DD + k0 + kq);
                    AS(kq + 0, r) = v.x; AS(kq + 1, r) = v.y;
                    AS(kq + 2, r) = v.z; AS(kq + 3, r) = v.w;
                }
                if (tid < 512) {
                    int q = tid;
                    int r = q >> 2, kq = (q & 3) << 2;
                    float4 w = *(const float4*)(E + (size_t)(c0 + r) * DD + k0 + kq);
                    BS(kq + 0, r) = w.x; BS(kq + 1, r) = w.y;
                    BS(kq + 2, r) = w.z; BS(kq + 3, r) = w.w;
                }
                __syncthreads();
#pragma unroll
                for (int k = 0; k < 16; k++) {
                    float a[8], b[8];
#pragma unroll
                    for (int m = 0; m < 8; m++) a[m] = AS(k, ty + m * 32);
#pragma unroll
                    for (int n = 0; n < 8; n++) b[n] = BS(k, tx + n * 16);
#pragma unroll
                    for (int m = 0; m < 8; m++)
#pragma unroll
                        for (int n = 0; n < 8; n++)
                            acc[m][n] = fmaf(a[m], b[n], acc[m][n]);
                }
                __syncthreads();
            }
#pragma unroll
            for (int m = 0; m < 8; m++) {
                int   lr  = ty + m * 32;
                int   trg = tR[lr];
                float xr  = xR[lr];
                float mp = 0.f, mn = INFINITY;
#pragma unroll
                for (int n = 0; n < 8; n++) {
                    int   lc = hh * 128 + tx + n * 16;
                    float d2 = fmaxf(xr + xC[lc] - 2.f * acc[m][n], 0.f);
                    if (trg == tC[lc]) mp = fmaxf(mp, d2);
                    else               mn = fminf(mn, d2);
                }
#pragma unroll
                for (int o = 8; o > 0; o >>= 1) {
                    mp = fmaxf(mp, __shfl_xor_sync(0xFFFFFFFF, mp, o));
                    mn = fminf(mn, __shfl_xor_sync(0xFFFFFFFF, mn, o));
                }
                if (tx == 0) {
                    atomicMax((int*)&out[2 + r0 + lr],      __float_as_int(mp));
                    atomicMin((int*)&out[2 + NN + r0 + lr], __float_as_int(mn));
                }
            }
            __syncthreads();
        }
        __syncthreads();
    }
#undef AS
#undef BS
#endif
}

// ---------------- final deterministic reduce (+ d2 -> dist) ----------------
__global__ void k_finish(float* __restrict__ out) {
    int t = threadIdx.x;
    float str = 0.f, sce = 0.f;
    for (int i = t; i < NN; i += 256) {
        float ap = sqrtf(fmaxf(out[2 + i],      1e-12f));
        float an = sqrtf(fmaxf(out[2 + NN + i], 1e-12f));
        out[2 + i]      = ap;
        out[2 + NN + i] = an;
        str += fmaxf(ap - an + MARGIN_F, 0.f);
        sce += g_ce_row[i];
    }
    __shared__ float s1[256], s2[256];
    s1[t] = str; s2[t] = sce;
    __syncthreads();
    for (int o = 128; o > 0; o >>= 1) {
        if (t < o) { s1[t] += s1[t + o]; s2[t] += s2[t + o]; }
        __syncthreads();
    }
    if (t == 0) {
        out[0] = s2[0] / (float)NN;  // id_loss
        out[1] = s1[0] / (float)NN;  // tri_loss
    }
}

extern "C" void kernel_launch(void* const* d_in, const int* in_sizes, int n_in,
                              void* d_out, int out_size) {
    const float* E = (const float*)d_in[0];
    const float* P = (const float*)d_in[1];
    const int*   T = (const int*)d_in[2];
    float* out = (float*)d_out;

    static cudaStream_t s_side = 0;
    static cudaEvent_t  ev_fork = 0, ev_join = 0;
    if (!s_side) {
        cudaStreamCreateWithFlags(&s_side, cudaStreamNonBlocking);
        cudaEventCreateWithFlags(&ev_fork, cudaEventDisableTiming);
        cudaEventCreateWithFlags(&ev_join, cudaEventDisableTiming);
    }
    cudaFuncSetAttribute(k_dist, cudaFuncAttributeMaxDynamicSharedMemorySize,
                         DSMEM_BYTES);

    k_init<<<(NN + 255) / 256, 256>>>(T, out);

    cudaEventRecord(ev_fork, 0);
    cudaStreamWaitEvent(s_side, ev_fork, 0);
    k_ce<<<NN, 256, 0, s_side>>>(P);
    cudaEventRecord(ev_join, s_side);

    k_xx<<<NN, 256>>>(E);
    k_dist<<<136, 512, DSMEM_BYTES>>>(E, out);

    cudaStreamWaitEvent(0, ev_join, 0);
    k_finish<<<1, 256>>>(out);
}